// round 1
// baseline (speedup 1.0000x reference)
#include <cuda_runtime.h>
#include <cuda_bf16.h>
#include <math.h>

// Problem constants (fixed-shape problem)
#define BB 8
#define CC_TOT 512
#define OO 512
#define SS 512
#define HH 64
#define WW 64
#define KK 3
#define TAPS 9

#define EPSV 1e-8f

// scale = 1/sqrt(C*K*K) = 1/sqrt(4608), lin_scale = 1/sqrt(512)
#define CONV_SCALE 0.014731391274719739f   // 1/sqrt(4608)
#define LIN_SCALE  0.044194173824159216f   // 1/sqrt(512)

// ---------------- scratch (static device globals; no allocation) -------------
__device__ float g_s[BB * CC_TOT];            // modulation s[b][c]
__device__ float g_mult[BB * OO];             // scale * demod[b][o]
__device__ float g_wsq[OO * CC_TOT];          // sum_k weight^2 [o][c]
__device__ float g_wT[CC_TOT * TAPS * OO];    // weight transposed to [c][tap][o]

// ---------------- kernel 1: modulation s = style @ (mw*lin)^T + bias ---------
__global__ void mod_kernel(const float* __restrict__ style,
                           const float* __restrict__ mw,
                           const float* __restrict__ mb) {
    int wid  = (blockIdx.x * blockDim.x + threadIdx.x) >> 5;   // 0..4095
    int lane = threadIdx.x & 31;
    int b = wid >> 9;
    int c = wid & 511;
    float sum = 0.f;
    const float* st = style + b * SS;
    const float* mwr = mw + c * SS;
#pragma unroll 4
    for (int j = lane; j < SS; j += 32)
        sum += st[j] * mwr[j];
#pragma unroll
    for (int off = 16; off; off >>= 1)
        sum += __shfl_xor_sync(0xFFFFFFFFu, sum, off);
    if (lane == 0)
        g_s[b * CC_TOT + c] = sum * LIN_SCALE + mb[c];
}

// ---------------- kernel 2: weight transpose + per-(o,c) squared sum ---------
__global__ void wprep_kernel(const float* __restrict__ w) {
    int idx = blockIdx.x * blockDim.x + threadIdx.x;   // 0 .. O*C-1
    if (idx >= OO * CC_TOT) return;
    int o = idx & 511;
    int c = idx >> 9;
    float sq = 0.f;
#pragma unroll
    for (int t = 0; t < TAPS; t++) {
        float v = w[(o * CC_TOT + c) * TAPS + t];
        g_wT[(c * TAPS + t) * OO + o] = v;
        sq += v * v;
    }
    g_wsq[o * CC_TOT + c] = sq;
}

// ---------------- kernel 3: demod multiplier ---------------------------------
__global__ void demod_kernel() {
    int wid  = (blockIdx.x * blockDim.x + threadIdx.x) >> 5;   // 0..4095
    int lane = threadIdx.x & 31;
    int b = wid >> 9;
    int o = wid & 511;
    float sum = 0.f;
    const float* sb = g_s + b * CC_TOT;
    const float* wq = g_wsq + o * CC_TOT;
#pragma unroll 4
    for (int j = lane; j < CC_TOT; j += 32) {
        float sv = sb[j];
        sum += wq[j] * sv * sv;
    }
#pragma unroll
    for (int off = 16; off; off >>= 1)
        sum += __shfl_xor_sync(0xFFFFFFFFu, sum, off);
    if (lane == 0)
        g_mult[b * OO + o] =
            CONV_SCALE * rsqrtf(CONV_SCALE * CONV_SCALE * sum + EPSV);
}

// ---------------- kernel 4: main conv ----------------------------------------
// Block: 256 threads. Output tile: 64 o-channels x (4 rows x 16 cols) pixels.
// Each thread: 4 o x 4 px (1 row, 4 contiguous cols). K-loop over channels in
// chunks of CHK, with s[b,c] fused into the X-tile load and scale*demod[b,o]
// applied in the epilogue.
#define CHK 8
#define XPAD 19   // 6x19 padded halo rows -> conflict-free LDS pattern

__global__ __launch_bounds__(256) void conv_kernel(
    const float* __restrict__ x, float* __restrict__ out) {
    __shared__ float Ws[CHK][TAPS][64];   // 18432 B
    __shared__ float Xs[CHK][6][XPAD];    //  3648 B

    int b        = blockIdx.z;
    int o_base   = blockIdx.y * 64;
    int tile     = blockIdx.x;            // 64 tiles: 16 row-tiles x 4 col-tiles
    int row_base = (tile >> 2) * 4;
    int col_base = (tile & 3) * 16;

    int tid = threadIdx.x;
    int og  = tid >> 4;                   // 0..15 -> 4 o's each
    int pg  = tid & 15;                   // 0..15 -> 4 px each
    int pr  = pg >> 2;                    // pixel row within tile (0..3)
    int pc  = (pg & 3) * 4;               // pixel col within tile (0,4,8,12)

    float acc[4][4] = {};

    const float* sb = g_s + b * CC_TOT;
    const float* xb = x + (size_t)b * CC_TOT * HH * WW;

    for (int c0 = 0; c0 < CC_TOT; c0 += CHK) {
        // ---- fill weight tile: g_wT is [c][tap][o], coalesced in o ----
        for (int i = tid; i < CHK * TAPS * 64; i += 256) {
            int o    = i & 63;
            int rest = i >> 6;
            int tap  = rest % TAPS;
            int c    = rest / TAPS;
            Ws[c][tap][o] = g_wT[((c0 + c) * TAPS + tap) * OO + o_base + o];
        }
        // ---- fill input halo tile, fused s[b,c] multiply, zero padding ----
        for (int i = tid; i < CHK * 6 * 18; i += 256) {
            int col  = i % 18;
            int rest = i / 18;
            int r    = rest % 6;
            int c    = rest / 6;
            int gr = row_base + r - 1;
            int gc = col_base + col - 1;
            float v = 0.f;
            if ((unsigned)gr < (unsigned)HH && (unsigned)gc < (unsigned)WW)
                v = xb[((c0 + c) * HH + gr) * WW + gc];
            Xs[c][r][col] = v * sb[c0 + c];
        }
        __syncthreads();

        // ---- compute ----
#pragma unroll
        for (int c = 0; c < CHK; c++) {
            float xr[3][6];
#pragma unroll
            for (int r = 0; r < 3; r++)
#pragma unroll
                for (int j = 0; j < 6; j++)
                    xr[r][j] = Xs[c][pr + r][pc + j];
#pragma unroll
            for (int kh = 0; kh < 3; kh++) {
#pragma unroll
                for (int kw = 0; kw < 3; kw++) {
                    float4 w4 = *(const float4*)&Ws[c][kh * 3 + kw][og * 4];
#pragma unroll
                    for (int j = 0; j < 4; j++) {
                        float xv = xr[kh][kw + j];
                        acc[0][j] = fmaf(w4.x, xv, acc[0][j]);
                        acc[1][j] = fmaf(w4.y, xv, acc[1][j]);
                        acc[2][j] = fmaf(w4.z, xv, acc[2][j]);
                        acc[3][j] = fmaf(w4.w, xv, acc[3][j]);
                    }
                }
            }
        }
        __syncthreads();
    }

    // ---- epilogue: apply scale*demod, vectorized store ----
#pragma unroll
    for (int oi = 0; oi < 4; oi++) {
        int o = o_base + og * 4 + oi;
        float m = g_mult[b * OO + o];
        float4 v;
        v.x = acc[oi][0] * m;
        v.y = acc[oi][1] * m;
        v.z = acc[oi][2] * m;
        v.w = acc[oi][3] * m;
        *(float4*)&out[(((size_t)b * OO + o) * HH + row_base + pr) * WW +
                       col_base + pc] = v;
    }
}

// ---------------- launch -----------------------------------------------------
extern "C" void kernel_launch(void* const* d_in, const int* in_sizes, int n_in,
                              void* d_out, int out_size) {
    const float* input  = (const float*)d_in[0];   // [B,C,H,W]
    const float* style  = (const float*)d_in[1];   // [B,S]
    const float* weight = (const float*)d_in[2];   // [1,O,C,3,3]
    const float* mw     = (const float*)d_in[3];   // [C,S]
    const float* mb     = (const float*)d_in[4];   // [C]
    float* out = (float*)d_out;

    // 1) modulation s[b,c] : 4096 warps
    mod_kernel<<<512, 256>>>(style, mw, mb);
    // 2) weight transpose + squared sums
    wprep_kernel<<<(OO * CC_TOT + 255) / 256, 256>>>(weight);
    // 3) demod multipliers : 4096 warps
    demod_kernel<<<512, 256>>>();
    // 4) conv: grid (64 spatial tiles, 8 o-tiles, 8 batch)
    dim3 grid(64, 8, 8);
    conv_kernel<<<grid, 256>>>(input, out);
}

// round 4
// speedup vs baseline: 6.4025x; 6.4025x over previous
#include <cuda_runtime.h>
#include <cuda_fp16.h>
#include <cstdint>
#include <math.h>

#define BB 8
#define CC_TOT 512
#define OO 512
#define SS 512
#define HH 64
#define WW 64
#define TAPS 9

#define EPSV 1e-8f
#define CONV_SCALE 0.014731391274719739f   // 1/sqrt(4608)
#define LIN_SCALE  0.044194173824159216f   // 1/sqrt(512)

// ---------------- device scratch (static, no allocation) ---------------------
__device__ float g_s[BB * CC_TOT];                         // modulation s[b][c]
__device__ float g_mult[BB * OO];                          // scale*demod[b][o]
__device__ float g_wsq[OO * CC_TOT];                       // sum_k w^2 [o][c]
__device__ __align__(16) __half g_wh[TAPS * OO * CC_TOT];  // fp16 W [t][o][c]
__device__ __align__(16) __half g_xt[(size_t)BB * HH * WW * CC_TOT]; // fp16 x*s [b][hw][c]

// ---------------- prep kernels ----------------------------------------------
__global__ void mod_kernel(const float* __restrict__ style,
                           const float* __restrict__ mw,
                           const float* __restrict__ mb) {
    int wid = (blockIdx.x * blockDim.x + threadIdx.x) >> 5;
    int lane = threadIdx.x & 31;
    int b = wid >> 9, c = wid & 511;
    float sum = 0.f;
    const float* st = style + b * SS;
    const float* mwr = mw + c * SS;
#pragma unroll 4
    for (int j = lane; j < SS; j += 32) sum += st[j] * mwr[j];
#pragma unroll
    for (int off = 16; off; off >>= 1) sum += __shfl_xor_sync(0xFFFFFFFFu, sum, off);
    if (lane == 0) g_s[b * CC_TOT + c] = sum * LIN_SCALE + mb[c];
}

__global__ void wprep_kernel(const float* __restrict__ w) {
    int idx = blockIdx.x * blockDim.x + threadIdx.x;   // o*512 + c
    if (idx >= OO * CC_TOT) return;
    int c = idx & 511, o = idx >> 9;
    const float* wr = w + ((size_t)o * CC_TOT + c) * TAPS;
    float sq = 0.f;
#pragma unroll
    for (int t = 0; t < TAPS; t++) {
        float v = wr[t];
        sq += v * v;
        g_wh[((size_t)t * OO + o) * CC_TOT + c] = __float2half(v);
    }
    g_wsq[o * CC_TOT + c] = sq;
}

__global__ void demod_kernel() {
    int wid = (blockIdx.x * blockDim.x + threadIdx.x) >> 5;
    int lane = threadIdx.x & 31;
    int b = wid >> 9, o = wid & 511;
    float sum = 0.f;
    const float* sb = g_s + b * CC_TOT;
    const float* wq = g_wsq + o * CC_TOT;
#pragma unroll 4
    for (int j = lane; j < CC_TOT; j += 32) {
        float sv = sb[j];
        sum += wq[j] * sv * sv;
    }
#pragma unroll
    for (int off = 16; off; off >>= 1) sum += __shfl_xor_sync(0xFFFFFFFFu, sum, off);
    if (lane == 0)
        g_mult[b * OO + o] = CONV_SCALE * rsqrtf(CONV_SCALE * CONV_SCALE * sum + EPSV);
}

// x [b][c][hw] fp32 -> g_xt [b][hw][c] fp16 with s[b][c] fused (32x32 smem tiles)
__global__ void xprep_kernel(const float* __restrict__ x) {
    __shared__ float tile[32][33];
    int b  = blockIdx.z;
    int hw0 = blockIdx.y * 32;
    int c0  = blockIdx.x * 32;
    int tx = threadIdx.x, ty = threadIdx.y;   // 32 x 8
#pragma unroll
    for (int j = 0; j < 4; j++) {
        int c = c0 + ty + j * 8;
        tile[ty + j * 8][tx] =
            x[(((size_t)b * CC_TOT + c) << 12) + hw0 + tx] * g_s[b * CC_TOT + c];
    }
    __syncthreads();
#pragma unroll
    for (int j = 0; j < 4; j++) {
        int hw = hw0 + ty + j * 8;
        g_xt[(((size_t)b << 12) + hw) * CC_TOT + c0 + tx] =
            __float2half(tile[tx][ty + j * 8]);
    }
}

// ---------------- main mma.sync kernel ---------------------------------------
// CTA: 256 thr, tile M=128 (o) x N=128 (px = 2 rows x 64) x K=32 per chunk.
// 144 chunks = 9 taps x 16 c-chunks. K-major smem rows padded to 40 halfs (80B).
#define ROWB 80            // bytes per smem row (32 halfs + 8 pad)
#define BUFB 20480         // As(10240) + Bs(10240)

__device__ __forceinline__ uint32_t smem_u32(const void* p) {
    uint32_t a;
    asm("{ .reg .u64 t; cvta.to.shared.u64 t, %1; cvt.u32.u64 %0, t; }"
        : "=r"(a) : "l"(p));
    return a;
}
#define CP_ASYNC16(dst, src, vld) \
    asm volatile("cp.async.cg.shared.global [%0], [%1], 16, %2;" \
                 :: "r"(dst), "l"(src), "r"(vld) : "memory")
#define CP_COMMIT() asm volatile("cp.async.commit_group;" ::: "memory")
#define CP_WAIT0()  asm volatile("cp.async.wait_group 0;" ::: "memory")
#define LDSM4(r0, r1, r2, r3, a) \
    asm volatile("ldmatrix.sync.aligned.m8n8.x4.shared.b16 {%0,%1,%2,%3}, [%4];" \
                 : "=r"(r0), "=r"(r1), "=r"(r2), "=r"(r3) : "r"(a))
#define MMA16816(d0, d1, d2, d3, a0, a1, a2, a3, b0, b1) \
    asm volatile("mma.sync.aligned.m16n8k16.row.col.f32.f16.f16.f32 " \
                 "{%0,%1,%2,%3}, {%4,%5,%6,%7}, {%8,%9}, {%0,%1,%2,%3};" \
                 : "+f"(d0), "+f"(d1), "+f"(d2), "+f"(d3) \
                 : "r"(a0), "r"(a1), "r"(a2), "r"(a3), "r"(b0), "r"(b1))

__global__ void __launch_bounds__(256, 2) conv_mma_kernel(
    float* __restrict__ out) {
    __shared__ __align__(16) char smem[2][BUFB];

    int tid  = threadIdx.x;
    int wid  = tid >> 5;
    int lane = tid & 31;
    int warp_m = wid >> 2;            // 0..1  (64 o each)
    int warp_n = wid & 3;             // 0..3  (32 px each)

    int o_base = blockIdx.x * 128;
    int py     = blockIdx.y;          // 32 px tiles (2 rows each)
    int b      = blockIdx.z;
    int r0     = py * 2;

    uint32_t sm0 = smem_u32(&smem[0][0]);

    float acc[4][4][4];
#pragma unroll
    for (int i = 0; i < 4; i++)
#pragma unroll
        for (int j = 0; j < 4; j++)
#pragma unroll
            for (int k = 0; k < 4; k++) acc[i][j][k] = 0.f;

    // fill thread mapping: q0 = A (o = q/4, unit = q%4), q1 = B (px = q/4)
    int qa_o = tid >> 1;              // handles 2 units: (tid&1)*2, +1
    const __half* xb = g_xt + ((size_t)b << 12) * CC_TOT;

    // ---- fill issuer ----
    auto issue = [&](int i, int buf) {
        int t  = i >> 4;              // tap 0..8
        int c0 = (i & 15) << 5;       // c chunk
        uint32_t sA = sm0 + buf * BUFB;
        uint32_t sB = sA + 10240;
        // A: 128 o x 32 c  (2 x 16B per thread)
        const __half* wsrc = g_wh + (((size_t)t * OO + o_base + qa_o) * CC_TOT + c0);
#pragma unroll
        for (int u = 0; u < 2; u++) {
            int unit = (tid & 1) * 2 + u;
            CP_ASYNC16(sA + qa_o * ROWB + unit * 16, (const char*)(wsrc + unit * 8), 16);
        }
        // B: 128 px x 32 c (2 x 16B per thread), im2col with zero fill
        int dh = t / 3 - 1, dw = t % 3 - 1;
        int px = tid >> 1;
        int rr = px >> 6, ww = px & 63;
        int gr = r0 + rr + dh, gc = ww + dw;
        bool valid = ((unsigned)gr < (unsigned)HH) && ((unsigned)gc < (unsigned)WW);
        int gpx = valid ? (gr * 64 + gc) : 0;
        const __half* xsrc = xb + ((size_t)gpx * CC_TOT + c0);
        int vld = valid ? 16 : 0;
#pragma unroll
        for (int u = 0; u < 2; u++) {
            int unit = (tid & 1) * 2 + u;
            CP_ASYNC16(sB + px * ROWB + unit * 16, (const char*)(xsrc + unit * 8), vld);
        }
        CP_COMMIT();
    };

    issue(0, 0);

#pragma unroll 1
    for (int i = 0; i < 144; i++) {
        int buf = i & 1;
        CP_WAIT0();
        __syncthreads();
        if (i + 1 < 144) issue(i + 1, buf ^ 1);

        uint32_t sA = sm0 + buf * BUFB;
        uint32_t sB = sA + 10240;
        uint32_t arow = sA + (uint32_t)(warp_m * 64 + (lane & 15)) * ROWB + ((lane >> 4) * 16);
        uint32_t brow = sB + (uint32_t)(warp_n * 32 + (lane & 15)) * ROWB + ((lane >> 4) * 16);

#pragma unroll
        for (int ks = 0; ks < 2; ks++) {
            uint32_t koff = ks * 32;
            uint32_t a[4][4], bm[2][4];
#pragma unroll
            for (int mi = 0; mi < 4; mi++)
                LDSM4(a[mi][0], a[mi][1], a[mi][2], a[mi][3],
                      arow + (uint32_t)(mi * 16) * ROWB + koff);
#pragma unroll
            for (int ni = 0; ni < 2; ni++)
                LDSM4(bm[ni][0], bm[ni][1], bm[ni][2], bm[ni][3],
                      brow + (uint32_t)(ni * 16) * ROWB + koff);
#pragma unroll
            for (int mi = 0; mi < 4; mi++) {
#pragma unroll
                for (int ni = 0; ni < 2; ni++) {
                    MMA16816(acc[mi][ni * 2][0], acc[mi][ni * 2][1],
                             acc[mi][ni * 2][2], acc[mi][ni * 2][3],
                             a[mi][0], a[mi][1], a[mi][2], a[mi][3],
                             bm[ni][0], bm[ni][2]);
                    MMA16816(acc[mi][ni * 2 + 1][0], acc[mi][ni * 2 + 1][1],
                             acc[mi][ni * 2 + 1][2], acc[mi][ni * 2 + 1][3],
                             a[mi][0], a[mi][1], a[mi][2], a[mi][3],
                             bm[ni][1], bm[ni][3]);
                }
            }
        }
    }

    // ---- epilogue: scale by demod, store ----
    __syncthreads();
#pragma unroll
    for (int mi = 0; mi < 4; mi++) {
#pragma unroll
        for (int half = 0; half < 2; half++) {
            int o = o_base + warp_m * 64 + mi * 16 + (lane >> 2) + half * 8;
            float m = g_mult[b * OO + o];
            float* op = out + (((size_t)b * OO + o) << 12) + py * 128 +
                        warp_n * 32 + (lane & 3) * 2;
#pragma unroll
            for (int ni = 0; ni < 4; ni++) {
                float2 v;
                v.x = acc[mi][ni][half * 2 + 0] * m;
                v.y = acc[mi][ni][half * 2 + 1] * m;
                *(float2*)(op + ni * 8) = v;
            }
        }
    }
}

// ---------------- launch -----------------------------------------------------
extern "C" void kernel_launch(void* const* d_in, const int* in_sizes, int n_in,
                              void* d_out, int out_size) {
    const float* input  = (const float*)d_in[0];   // [B,C,H,W]
    const float* style  = (const float*)d_in[1];   // [B,S]
    const float* weight = (const float*)d_in[2];   // [1,O,C,3,3]
    const float* mw     = (const float*)d_in[3];   // [C,S]
    const float* mb     = (const float*)d_in[4];   // [C]
    float* out = (float*)d_out;

    mod_kernel<<<512, 256>>>(style, mw, mb);
    wprep_kernel<<<(OO * CC_TOT + 255) / 256, 256>>>(weight);
    demod_kernel<<<512, 256>>>();
    {
        dim3 gb(16, 128, 8), tb(32, 8);
        xprep_kernel<<<gb, tb>>>(input);
    }
    dim3 grid(4, 32, 8);   // (o tiles, px tiles, batch)
    conv_mma_kernel<<<grid, 256>>>(out);
}

// round 5
// speedup vs baseline: 6.9015x; 1.0779x over previous
#include <cuda_runtime.h>
#include <cuda_fp16.h>
#include <cstdint>
#include <math.h>

#define BB 8
#define CC_TOT 512
#define OO 512
#define SS 512
#define HH 64
#define WW 64
#define TAPS 9

#define EPSV 1e-8f
#define CONV_SCALE 0.014731391274719739f   // 1/sqrt(4608)
#define LIN_SCALE  0.044194173824159216f   // 1/sqrt(512)

// ---------------- device scratch (static, no allocation) ---------------------
__device__ float g_s[BB * CC_TOT];                         // modulation s[b][c]
__device__ float g_mult[BB * OO];                          // scale*demod[b][o]
__device__ float g_wsq[OO * CC_TOT];                       // sum_k w^2 [o][c]
__device__ __align__(16) __half g_wh[TAPS * OO * CC_TOT];  // fp16 W [t][o][c]
__device__ __align__(16) __half g_xt[(size_t)BB * HH * WW * CC_TOT]; // fp16 x*s [b][hw][c]

// ---------------- prep kernels ----------------------------------------------
__global__ void mod_kernel(const float* __restrict__ style,
                           const float* __restrict__ mw,
                           const float* __restrict__ mb) {
    int wid = (blockIdx.x * blockDim.x + threadIdx.x) >> 5;
    int lane = threadIdx.x & 31;
    int b = wid >> 9, c = wid & 511;
    float sum = 0.f;
    const float* st = style + b * SS;
    const float* mwr = mw + c * SS;
#pragma unroll 4
    for (int j = lane; j < SS; j += 32) sum += st[j] * mwr[j];
#pragma unroll
    for (int off = 16; off; off >>= 1) sum += __shfl_xor_sync(0xFFFFFFFFu, sum, off);
    if (lane == 0) g_s[b * CC_TOT + c] = sum * LIN_SCALE + mb[c];
}

__global__ void wprep_kernel(const float* __restrict__ w) {
    int idx = blockIdx.x * blockDim.x + threadIdx.x;   // o*512 + c
    if (idx >= OO * CC_TOT) return;
    int c = idx & 511, o = idx >> 9;
    const float* wr = w + ((size_t)o * CC_TOT + c) * TAPS;
    float sq = 0.f;
#pragma unroll
    for (int t = 0; t < TAPS; t++) {
        float v = wr[t];
        sq += v * v;
        g_wh[((size_t)t * OO + o) * CC_TOT + c] = __float2half(v);
    }
    g_wsq[o * CC_TOT + c] = sq;
}

__global__ void demod_kernel() {
    int wid = (blockIdx.x * blockDim.x + threadIdx.x) >> 5;
    int lane = threadIdx.x & 31;
    int b = wid >> 9, o = wid & 511;
    float sum = 0.f;
    const float* sb = g_s + b * CC_TOT;
    const float* wq = g_wsq + o * CC_TOT;
#pragma unroll 4
    for (int j = lane; j < CC_TOT; j += 32) {
        float sv = sb[j];
        sum += wq[j] * sv * sv;
    }
#pragma unroll
    for (int off = 16; off; off >>= 1) sum += __shfl_xor_sync(0xFFFFFFFFu, sum, off);
    if (lane == 0)
        g_mult[b * OO + o] = CONV_SCALE * rsqrtf(CONV_SCALE * CONV_SCALE * sum + EPSV);
}

// x [b][c][hw] fp32 -> g_xt [b][hw][c] fp16 with s[b][c] fused (32x32 smem tiles)
__global__ void xprep_kernel(const float* __restrict__ x) {
    __shared__ float tile[32][33];
    int b  = blockIdx.z;
    int hw0 = blockIdx.y * 32;
    int c0  = blockIdx.x * 32;
    int tx = threadIdx.x, ty = threadIdx.y;   // 32 x 8
#pragma unroll
    for (int j = 0; j < 4; j++) {
        int c = c0 + ty + j * 8;
        tile[ty + j * 8][tx] =
            x[(((size_t)b * CC_TOT + c) << 12) + hw0 + tx] * g_s[b * CC_TOT + c];
    }
    __syncthreads();
#pragma unroll
    for (int j = 0; j < 4; j++) {
        int hw = hw0 + ty + j * 8;
        g_xt[(((size_t)b << 12) + hw) * CC_TOT + c0 + tx] =
            __float2half(tile[tx][ty + j * 8]);
    }
}

// ---------------- main mma.sync kernel ---------------------------------------
// CTA: 512 thr (16 warps), tile M=128 (o) x N=256 (px = 4 rows x 64).
// K loop: 16 c-chunks of 32; inner 9 taps reuse one padded B tile via
// ldmatrix address shifting. A double-buffered per tap, B per c-chunk.
#define ROWB 80                 // bytes per smem row (32 halfs + 8 pad)
#define A_BUF 10240             // 128 rows * 80
#define B_ROWS 396              // 6 x 66 padded px rows
#define B_BUF 31680             // 396 * 80
#define SM_B_OFF (2 * A_BUF)    // 20480
#define SMEM_TOTAL (2 * A_BUF + 2 * B_BUF)   // 83840

__device__ __forceinline__ uint32_t smem_u32(const void* p) {
    uint32_t a;
    asm("{ .reg .u64 t; cvta.to.shared.u64 t, %1; cvt.u32.u64 %0, t; }"
        : "=r"(a) : "l"(p));
    return a;
}
#define CP_ASYNC16(dst, src) \
    asm volatile("cp.async.cg.shared.global [%0], [%1], 16;" \
                 :: "r"(dst), "l"(src) : "memory")
#define CP_COMMIT() asm volatile("cp.async.commit_group;" ::: "memory")
#define CP_WAIT(n)  asm volatile("cp.async.wait_group %0;" :: "n"(n) : "memory")
#define LDSM4(r0, r1, r2, r3, a) \
    asm volatile("ldmatrix.sync.aligned.m8n8.x4.shared.b16 {%0,%1,%2,%3}, [%4];" \
                 : "=r"(r0), "=r"(r1), "=r"(r2), "=r"(r3) : "r"(a))
#define MMA16816(d0, d1, d2, d3, a0, a1, a2, a3, b0, b1) \
    asm volatile("mma.sync.aligned.m16n8k16.row.col.f32.f16.f16.f32 " \
                 "{%0,%1,%2,%3}, {%4,%5,%6,%7}, {%8,%9}, {%0,%1,%2,%3};" \
                 : "+f"(d0), "+f"(d1), "+f"(d2), "+f"(d3) \
                 : "r"(a0), "r"(a1), "r"(a2), "r"(a3), "r"(b0), "r"(b1))

__global__ void __launch_bounds__(512, 1) conv_mma_kernel(
    float* __restrict__ out) {
    extern __shared__ __align__(16) char sm[];
    uint32_t smb = smem_u32(sm);

    int tid  = threadIdx.x;
    int wid  = tid >> 5;
    int lane = tid & 31;
    int warp_m = wid >> 3;            // 0..1  (64 o each)
    int warp_n = wid & 7;             // 0..7  (32 px each)

    int o_base = blockIdx.x * 128;
    int py     = blockIdx.y;          // 16 px tiles (4 rows each)
    int b      = blockIdx.z;
    int r0     = py * 4;

    // ---- zero both B buffers (pads + halo stay zero forever) ----
    for (int j = tid; j < (2 * B_BUF) / 16; j += 512)
        *(uint4*)(sm + SM_B_OFF + j * 16) = make_uint4(0, 0, 0, 0);
    __syncthreads();

    float acc[4][4][4];
#pragma unroll
    for (int i = 0; i < 4; i++)
#pragma unroll
        for (int j = 0; j < 4; j++)
#pragma unroll
            for (int k = 0; k < 4; k++) acc[i][j][k] = 0.f;

    // ---- fill helpers ----
    // A: 128 o x 32 c, 1 cp.async per thread
    int a_o = tid >> 2, a_u = tid & 3;
    auto issueA = [&](int t, int c0, uint32_t dst) {
        const __half* src =
            g_wh + (((size_t)t * OO + o_base + a_o) * CC_TOT + c0) + a_u * 8;
        CP_ASYNC16(dst + (uint32_t)(a_o * ROWB + a_u * 16), (const char*)src);
        CP_COMMIT();
    };
    // B: 6 rows x 64 cols x 32 c, 3 cp.async per thread, row-valid predicated
    const __half* xb = g_xt + (((size_t)b) << 12) * CC_TOT;
    auto issueB = [&](int c0, uint32_t dst) {
#pragma unroll
        for (int k = 0; k < 3; k++) {
            int q = tid + k * 512;          // 0..1535
            int unit = q & 3, pxl = q >> 2; // pxl 0..383
            int r = pxl >> 6, col = pxl & 63;
            int gr = r0 - 1 + r;
            if ((unsigned)gr < (unsigned)HH) {
                const __half* src = xb + ((size_t)(gr * 64 + col) * CC_TOT + c0) + unit * 8;
                CP_ASYNC16(dst + (uint32_t)((r * 66 + col + 1) * ROWB + unit * 16),
                           (const char*)src);
            }
        }
        CP_COMMIT();
    };

    // ---- ldmatrix base offsets ----
    uint32_t a_off = (uint32_t)((warp_m * 64 + (lane & 15)) * ROWB + (lane >> 4) * 16);
    uint32_t b_off[2];
#pragma unroll
    for (int ni = 0; ni < 2; ni++) {
        int p = warp_n * 32 + ni * 16 + (lane & 15);
        int r = p >> 6, col = p & 63;
        b_off[ni] = (uint32_t)(((r + 1) * 66 + col + 1) * ROWB + (lane >> 4) * 16);
    }
    int tapoff[9];
#pragma unroll
    for (int t = 0; t < 9; t++)
        tapoff[t] = ((t / 3 - 1) * 66 + (t % 3 - 1)) * ROWB;

    // ---- prologue: B chunk 0 + A(tap0, chunk0) ----
    issueB(0, smb + SM_B_OFF);
    issueA(0, 0, smb);

    int cc = 0, tap = 0;
#pragma unroll 1
    for (int i = 0; i < 144; i++) {
        if (tap == 7) { CP_WAIT(1); } else { CP_WAIT(0); }
        __syncthreads();

        // issue future fills (into the non-active buffers)
        uint32_t nA = smb + (uint32_t)(((i + 1) & 1) * A_BUF);
        if (tap < 8) {
            issueA(tap + 1, cc << 5, nA);
            if (tap == 6 && cc + 1 < 16)
                issueB((cc + 1) << 5, smb + SM_B_OFF + (uint32_t)(((cc + 1) & 1) * B_BUF));
        } else if (cc + 1 < 16) {
            issueA(0, (cc + 1) << 5, nA);
        }

        // ---- MMA on A[i&1], B[cc&1] with tap shift ----
        uint32_t sA = smb + (uint32_t)((i & 1) * A_BUF);
        uint32_t sB = smb + SM_B_OFF + (uint32_t)((cc & 1) * B_BUF) + tapoff[tap];

#pragma unroll
        for (int ks = 0; ks < 2; ks++) {
            uint32_t koff = ks * 32;
            uint32_t a[4][4], bm[2][4];
#pragma unroll
            for (int mi = 0; mi < 4; mi++)
                LDSM4(a[mi][0], a[mi][1], a[mi][2], a[mi][3],
                      sA + a_off + (uint32_t)(mi * 16 * ROWB) + koff);
#pragma unroll
            for (int ni = 0; ni < 2; ni++)
                LDSM4(bm[ni][0], bm[ni][1], bm[ni][2], bm[ni][3],
                      sB + b_off[ni] + koff);
#pragma unroll
            for (int mi = 0; mi < 4; mi++) {
#pragma unroll
                for (int ni = 0; ni < 2; ni++) {
                    MMA16816(acc[mi][ni * 2][0], acc[mi][ni * 2][1],
                             acc[mi][ni * 2][2], acc[mi][ni * 2][3],
                             a[mi][0], a[mi][1], a[mi][2], a[mi][3],
                             bm[ni][0], bm[ni][2]);
                    MMA16816(acc[mi][ni * 2 + 1][0], acc[mi][ni * 2 + 1][1],
                             acc[mi][ni * 2 + 1][2], acc[mi][ni * 2 + 1][3],
                             a[mi][0], a[mi][1], a[mi][2], a[mi][3],
                             bm[ni][1], bm[ni][3]);
                }
            }
        }

        if (++tap == 9) { tap = 0; ++cc; }
    }

    // ---- epilogue: scale by demod, store ----
#pragma unroll
    for (int mi = 0; mi < 4; mi++) {
#pragma unroll
        for (int half = 0; half < 2; half++) {
            int o = o_base + warp_m * 64 + mi * 16 + (lane >> 2) + half * 8;
            float m = g_mult[b * OO + o];
            float* op = out + (((size_t)b * OO + o) << 12) + py * 256 +
                        warp_n * 32 + (lane & 3) * 2;
#pragma unroll
            for (int ni = 0; ni < 4; ni++) {
                float2 v;
                v.x = acc[mi][ni][half * 2 + 0] * m;
                v.y = acc[mi][ni][half * 2 + 1] * m;
                *(float2*)(op + ni * 8) = v;
            }
        }
    }
}

// ---------------- launch -----------------------------------------------------
extern "C" void kernel_launch(void* const* d_in, const int* in_sizes, int n_in,
                              void* d_out, int out_size) {
    const float* input  = (const float*)d_in[0];   // [B,C,H,W]
    const float* style  = (const float*)d_in[1];   // [B,S]
    const float* weight = (const float*)d_in[2];   // [1,O,C,3,3]
    const float* mw     = (const float*)d_in[3];   // [C,S]
    const float* mb     = (const float*)d_in[4];   // [C]
    float* out = (float*)d_out;

    mod_kernel<<<512, 256>>>(style, mw, mb);
    wprep_kernel<<<(OO * CC_TOT + 255) / 256, 256>>>(weight);
    demod_kernel<<<512, 256>>>();
    {
        dim3 gb(16, 128, 8), tb(32, 8);
        xprep_kernel<<<gb, tb>>>(input);
    }
    cudaFuncSetAttribute(conv_mma_kernel,
                         cudaFuncAttributeMaxDynamicSharedMemorySize, SMEM_TOTAL);
    dim3 grid(4, 16, 8);   // (o tiles, px tiles, batch)
    conv_mma_kernel<<<grid, 512, SMEM_TOTAL>>>(out);
}

// round 6
// speedup vs baseline: 7.5495x; 1.0939x over previous
#include <cuda_runtime.h>
#include <cuda_fp16.h>
#include <cstdint>
#include <math.h>

#define BB 8
#define CC_TOT 512
#define OO 512
#define SS 512
#define HH 64
#define WW 64
#define TAPS 9

#define EPSV 1e-8f
#define CONV_SCALE 0.014731391274719739f   // 1/sqrt(4608)
#define LIN_SCALE  0.044194173824159216f   // 1/sqrt(512)

// ---------------- device scratch (static, no allocation) ---------------------
__device__ float g_s[BB * CC_TOT];                         // modulation s[b][c]
__device__ float g_mult[BB * OO];                          // scale*demod[b][o]
__device__ float g_wsq[OO * CC_TOT];                       // sum_k w^2 [o][c]
__device__ __align__(16) __half g_wh[TAPS * OO * CC_TOT];  // fp16 W [t][o][c]
__device__ __align__(16) __half g_xt[(size_t)BB * HH * WW * CC_TOT]; // fp16 x*s [b][hw][c]

// ---------------- prep kernels ----------------------------------------------
__global__ void mod_kernel(const float* __restrict__ style,
                           const float* __restrict__ mw,
                           const float* __restrict__ mb) {
    int wid = (blockIdx.x * blockDim.x + threadIdx.x) >> 5;
    int lane = threadIdx.x & 31;
    int b = wid >> 9, c = wid & 511;
    float sum = 0.f;
    const float* st = style + b * SS;
    const float* mwr = mw + c * SS;
#pragma unroll 4
    for (int j = lane; j < SS; j += 32) sum += st[j] * mwr[j];
#pragma unroll
    for (int off = 16; off; off >>= 1) sum += __shfl_xor_sync(0xFFFFFFFFu, sum, off);
    if (lane == 0) g_s[b * CC_TOT + c] = sum * LIN_SCALE + mb[c];
}

__global__ void wprep_kernel(const float* __restrict__ w) {
    int idx = blockIdx.x * blockDim.x + threadIdx.x;   // o*512 + c
    if (idx >= OO * CC_TOT) return;
    int c = idx & 511, o = idx >> 9;
    const float* wr = w + ((size_t)o * CC_TOT + c) * TAPS;
    float sq = 0.f;
#pragma unroll
    for (int t = 0; t < TAPS; t++) {
        float v = wr[t];
        sq += v * v;
        g_wh[((size_t)t * OO + o) * CC_TOT + c] = __float2half(v);
    }
    g_wsq[o * CC_TOT + c] = sq;
}

__global__ void demod_kernel() {
    int wid = (blockIdx.x * blockDim.x + threadIdx.x) >> 5;
    int lane = threadIdx.x & 31;
    int b = wid >> 9, o = wid & 511;
    float sum = 0.f;
    const float* sb = g_s + b * CC_TOT;
    const float* wq = g_wsq + o * CC_TOT;
#pragma unroll 4
    for (int j = lane; j < CC_TOT; j += 32) {
        float sv = sb[j];
        sum += wq[j] * sv * sv;
    }
#pragma unroll
    for (int off = 16; off; off >>= 1) sum += __shfl_xor_sync(0xFFFFFFFFu, sum, off);
    if (lane == 0)
        g_mult[b * OO + o] = CONV_SCALE * rsqrtf(CONV_SCALE * CONV_SCALE * sum + EPSV);
}

// x [b][c][hw] fp32 -> g_xt [b][hw][c] fp16 with s[b][c] fused (32x32 smem tiles)
__global__ void xprep_kernel(const float* __restrict__ x) {
    __shared__ float tile[32][33];
    int b  = blockIdx.z;
    int hw0 = blockIdx.y * 32;
    int c0  = blockIdx.x * 32;
    int tx = threadIdx.x, ty = threadIdx.y;   // 32 x 8
#pragma unroll
    for (int j = 0; j < 4; j++) {
        int c = c0 + ty + j * 8;
        tile[ty + j * 8][tx] =
            x[(((size_t)b * CC_TOT + c) << 12) + hw0 + tx] * g_s[b * CC_TOT + c];
    }
    __syncthreads();
#pragma unroll
    for (int j = 0; j < 4; j++) {
        int hw = hw0 + ty + j * 8;
        g_xt[(((size_t)b << 12) + hw) * CC_TOT + c0 + tx] =
            __float2half(tile[tx][ty + j * 8]);
    }
}

// ---------------- main mma.sync kernel ---------------------------------------
// CTA: 256 thr (8 warps), tile M=128 (o) x N=128 (px = 2 rows x 64), occ=2.
// K loop: 16 c-chunks of 32; inner 9 taps reuse one padded B tile via
// ldmatrix address shifting. A double-buffered per tap, B per c-chunk.
#define ROWB 80                 // bytes per smem row (32 halfs + 8 pad)
#define A_BUF 10240             // 128 rows * 80
#define B_ROWS 264              // 4 x 66 padded px rows
#define B_BUF 21120             // 264 * 80
#define SM_B_OFF (2 * A_BUF)    // 20480
#define SMEM_TOTAL (2 * A_BUF + 2 * B_BUF)   // 62720

__device__ __forceinline__ uint32_t smem_u32(const void* p) {
    uint32_t a;
    asm("{ .reg .u64 t; cvta.to.shared.u64 t, %1; cvt.u32.u64 %0, t; }"
        : "=r"(a) : "l"(p));
    return a;
}
#define CP_ASYNC16(dst, src) \
    asm volatile("cp.async.cg.shared.global [%0], [%1], 16;" \
                 :: "r"(dst), "l"(src) : "memory")
#define CP_COMMIT() asm volatile("cp.async.commit_group;" ::: "memory")
#define CP_WAIT(n)  asm volatile("cp.async.wait_group %0;" :: "n"(n) : "memory")
#define LDSM4(r0, r1, r2, r3, a) \
    asm volatile("ldmatrix.sync.aligned.m8n8.x4.shared.b16 {%0,%1,%2,%3}, [%4];" \
                 : "=r"(r0), "=r"(r1), "=r"(r2), "=r"(r3) : "r"(a))
#define MMA16816(d0, d1, d2, d3, a0, a1, a2, a3, b0, b1) \
    asm volatile("mma.sync.aligned.m16n8k16.row.col.f32.f16.f16.f32 " \
                 "{%0,%1,%2,%3}, {%4,%5,%6,%7}, {%8,%9}, {%0,%1,%2,%3};" \
                 : "+f"(d0), "+f"(d1), "+f"(d2), "+f"(d3) \
                 : "r"(a0), "r"(a1), "r"(a2), "r"(a3), "r"(b0), "r"(b1))

__global__ void __launch_bounds__(256, 2) conv_mma_kernel(
    float* __restrict__ out) {
    extern __shared__ __align__(16) char sm[];
    uint32_t smb = smem_u32(sm);

    int tid  = threadIdx.x;
    int wid  = tid >> 5;
    int lane = tid & 31;
    int warp_m = wid >> 2;            // 0..1  (64 o each)
    int warp_n = wid & 3;             // 0..3  (32 px each)

    int o_base = blockIdx.x * 128;
    int py     = blockIdx.y;          // 32 px tiles (2 rows each)
    int b      = blockIdx.z;
    int r0     = py * 2;

    // ---- zero both B buffers (pads + halo stay zero forever) ----
    for (int j = tid; j < (2 * B_BUF) / 16; j += 256)
        *(uint4*)(sm + SM_B_OFF + j * 16) = make_uint4(0, 0, 0, 0);
    __syncthreads();

    float acc[4][4][4];
#pragma unroll
    for (int i = 0; i < 4; i++)
#pragma unroll
        for (int j = 0; j < 4; j++)
#pragma unroll
            for (int k = 0; k < 4; k++) acc[i][j][k] = 0.f;

    // ---- fill helpers ----
    // A: 128 o x 32 c, 2 cp.async per thread
    int a_o = tid >> 1;
    auto issueA = [&](int t, int c0, uint32_t dst) {
        const __half* src =
            g_wh + (((size_t)t * OO + o_base + a_o) * CC_TOT + c0);
#pragma unroll
        for (int u = 0; u < 2; u++) {
            int unit = (tid & 1) * 2 + u;
            CP_ASYNC16(dst + (uint32_t)(a_o * ROWB + unit * 16),
                       (const char*)(src + unit * 8));
        }
        CP_COMMIT();
    };
    // B: 4 rows x 64 cols x 32 c, 4 cp.async per thread, row-valid predicated
    const __half* xb = g_xt + (((size_t)b) << 12) * CC_TOT;
    auto issueB = [&](int c0, uint32_t dst) {
#pragma unroll
        for (int k = 0; k < 4; k++) {
            int q = tid + k * 256;          // 0..1023
            int unit = q & 3, pxl = q >> 2; // pxl 0..255
            int r = pxl >> 6, col = pxl & 63;
            int gr = r0 - 1 + r;
            if ((unsigned)gr < (unsigned)HH) {
                const __half* src = xb + ((size_t)(gr * 64 + col) * CC_TOT + c0) + unit * 8;
                CP_ASYNC16(dst + (uint32_t)((r * 66 + col + 1) * ROWB + unit * 16),
                           (const char*)src);
            }
        }
        CP_COMMIT();
    };

    // ---- ldmatrix base offsets ----
    uint32_t a_off = (uint32_t)((warp_m * 64 + (lane & 15)) * ROWB + (lane >> 4) * 16);
    uint32_t b_off[2];
#pragma unroll
    for (int ni = 0; ni < 2; ni++) {
        int p = warp_n * 32 + ni * 16 + (lane & 15);
        int r = p >> 6, col = p & 63;
        b_off[ni] = (uint32_t)(((r + 1) * 66 + col + 1) * ROWB + (lane >> 4) * 16);
    }
    int tapoff[9];
#pragma unroll
    for (int t = 0; t < 9; t++)
        tapoff[t] = ((t / 3 - 1) * 66 + (t % 3 - 1)) * ROWB;

    // ---- prologue: B chunk 0 + A(tap0, chunk0) ----
    issueB(0, smb + SM_B_OFF);
    issueA(0, 0, smb);

    int cc = 0, tap = 0;
#pragma unroll 1
    for (int i = 0; i < 144; i++) {
        if (tap == 7) { CP_WAIT(1); } else { CP_WAIT(0); }
        __syncthreads();

        // issue future fills (into the non-active buffers)
        uint32_t nA = smb + (uint32_t)(((i + 1) & 1) * A_BUF);
        if (tap < 8) {
            issueA(tap + 1, cc << 5, nA);
            if (tap == 6 && cc + 1 < 16)
                issueB((cc + 1) << 5, smb + SM_B_OFF + (uint32_t)(((cc + 1) & 1) * B_BUF));
        } else if (cc + 1 < 16) {
            issueA(0, (cc + 1) << 5, nA);
        }

        // ---- MMA on A[i&1], B[cc&1] with tap shift ----
        uint32_t sA = smb + (uint32_t)((i & 1) * A_BUF);
        uint32_t sB = smb + SM_B_OFF + (uint32_t)((cc & 1) * B_BUF) + tapoff[tap];

#pragma unroll
        for (int ks = 0; ks < 2; ks++) {
            uint32_t koff = ks * 32;
            uint32_t a[4][4], bm[2][4];
#pragma unroll
            for (int mi = 0; mi < 4; mi++)
                LDSM4(a[mi][0], a[mi][1], a[mi][2], a[mi][3],
                      sA + a_off + (uint32_t)(mi * 16 * ROWB) + koff);
#pragma unroll
            for (int ni = 0; ni < 2; ni++)
                LDSM4(bm[ni][0], bm[ni][1], bm[ni][2], bm[ni][3],
                      sB + b_off[ni] + koff);
#pragma unroll
            for (int mi = 0; mi < 4; mi++) {
#pragma unroll
                for (int ni = 0; ni < 2; ni++) {
                    MMA16816(acc[mi][ni * 2][0], acc[mi][ni * 2][1],
                             acc[mi][ni * 2][2], acc[mi][ni * 2][3],
                             a[mi][0], a[mi][1], a[mi][2], a[mi][3],
                             bm[ni][0], bm[ni][2]);
                    MMA16816(acc[mi][ni * 2 + 1][0], acc[mi][ni * 2 + 1][1],
                             acc[mi][ni * 2 + 1][2], acc[mi][ni * 2 + 1][3],
                             a[mi][0], a[mi][1], a[mi][2], a[mi][3],
                             bm[ni][1], bm[ni][3]);
                }
            }
        }

        if (++tap == 9) { tap = 0; ++cc; }
    }

    // ---- epilogue: scale by demod, store ----
#pragma unroll
    for (int mi = 0; mi < 4; mi++) {
#pragma unroll
        for (int half = 0; half < 2; half++) {
            int o = o_base + warp_m * 64 + mi * 16 + (lane >> 2) + half * 8;
            float m = g_mult[b * OO + o];
            float* op = out + (((size_t)b * OO + o) << 12) + py * 128 +
                        warp_n * 32 + (lane & 3) * 2;
#pragma unroll
            for (int ni = 0; ni < 4; ni++) {
                float2 v;
                v.x = acc[mi][ni][half * 2 + 0] * m;
                v.y = acc[mi][ni][half * 2 + 1] * m;
                *(float2*)(op + ni * 8) = v;
            }
        }
    }
}

// ---------------- launch -----------------------------------------------------
extern "C" void kernel_launch(void* const* d_in, const int* in_sizes, int n_in,
                              void* d_out, int out_size) {
    const float* input  = (const float*)d_in[0];   // [B,C,H,W]
    const float* style  = (const float*)d_in[1];   // [B,S]
    const float* weight = (const float*)d_in[2];   // [1,O,C,3,3]
    const float* mw     = (const float*)d_in[3];   // [C,S]
    const float* mb     = (const float*)d_in[4];   // [C]
    float* out = (float*)d_out;

    mod_kernel<<<512, 256>>>(style, mw, mb);
    wprep_kernel<<<(OO * CC_TOT + 255) / 256, 256>>>(weight);
    demod_kernel<<<512, 256>>>();
    {
        dim3 gb(16, 128, 8), tb(32, 8);
        xprep_kernel<<<gb, tb>>>(input);
    }
    cudaFuncSetAttribute(conv_mma_kernel,
                         cudaFuncAttributeMaxDynamicSharedMemorySize, SMEM_TOTAL);
    dim3 grid(4, 32, 8);   // (o tiles, px tiles, batch)
    conv_mma_kernel<<<grid, 256, SMEM_TOTAL>>>(out);
}

// round 7
// speedup vs baseline: 10.6223x; 1.4070x over previous
#include <cuda_runtime.h>
#include <cuda_fp16.h>
#include <cstdint>
#include <math.h>

#define BB 8
#define CC_TOT 512
#define OO 512
#define SS 512
#define HH 64
#define WW 64
#define TAPS 9

#define EPSV 1e-8f
#define CONV_SCALE 0.014731391274719739f   // 1/sqrt(4608)
#define LIN_SCALE  0.044194173824159216f   // 1/sqrt(512)

// ---------------- device scratch (static, no allocation) ---------------------
__device__ float g_s[BB * CC_TOT];            // modulation s[b][c]
__device__ float g_mult[BB * OO];             // scale*demod[b][o]
__device__ float g_wsq[OO * CC_TOT];          // sum_k w^2 [o][c]
__device__ __align__(16) __half g_U[16 * OO * CC_TOT];                 // wino W [p][o][c]
__device__ __align__(16) __half g_V[(size_t)16 * BB * 1024 * CC_TOT];  // wino X [p*8+b][tile][c]
__device__ __align__(16) float  g_M[(size_t)16 * BB * OO * 1024];      // GEMM out [p*8+b][o][tile]

// ---------------- prep kernels ----------------------------------------------
__global__ void mod_kernel(const float* __restrict__ style,
                           const float* __restrict__ mw,
                           const float* __restrict__ mb) {
    int wid = (blockIdx.x * blockDim.x + threadIdx.x) >> 5;
    int lane = threadIdx.x & 31;
    int b = wid >> 9, c = wid & 511;
    float sum = 0.f;
    const float* st = style + b * SS;
    const float* mwr = mw + c * SS;
#pragma unroll 4
    for (int j = lane; j < SS; j += 32) sum += st[j] * mwr[j];
#pragma unroll
    for (int off = 16; off; off >>= 1) sum += __shfl_xor_sync(0xFFFFFFFFu, sum, off);
    if (lane == 0) g_s[b * CC_TOT + c] = sum * LIN_SCALE + mb[c];
}

// weight: wsq + Winograd transform U = G g G^T  -> fp16 [p][o][c]
__global__ void wprep_kernel(const float* __restrict__ w) {
    int idx = blockIdx.x * blockDim.x + threadIdx.x;   // o*512 + c
    if (idx >= OO * CC_TOT) return;
    int c = idx & 511, o = idx >> 9;
    const float* wr = w + ((size_t)o * CC_TOT + c) * TAPS;
    float g[3][3];
    float sq = 0.f;
#pragma unroll
    for (int i = 0; i < 3; i++)
#pragma unroll
        for (int j = 0; j < 3; j++) {
            float v = wr[i * 3 + j];
            g[i][j] = v;
            sq += v * v;
        }
    g_wsq[o * CC_TOT + c] = sq;
    // Gg (4x3)
    float a[4][3];
#pragma unroll
    for (int j = 0; j < 3; j++) {
        a[0][j] = g[0][j];
        a[1][j] = 0.5f * (g[0][j] + g[1][j] + g[2][j]);
        a[2][j] = 0.5f * (g[0][j] - g[1][j] + g[2][j]);
        a[3][j] = g[2][j];
    }
    // U = (Gg) G^T (4x4)
#pragma unroll
    for (int i = 0; i < 4; i++) {
        float u0 = a[i][0];
        float u1 = 0.5f * (a[i][0] + a[i][1] + a[i][2]);
        float u2 = 0.5f * (a[i][0] - a[i][1] + a[i][2]);
        float u3 = a[i][2];
        int p = i * 4;
        g_U[((size_t)(p + 0) * OO + o) * CC_TOT + c] = __float2half(u0);
        g_U[((size_t)(p + 1) * OO + o) * CC_TOT + c] = __float2half(u1);
        g_U[((size_t)(p + 2) * OO + o) * CC_TOT + c] = __float2half(u2);
        g_U[((size_t)(p + 3) * OO + o) * CC_TOT + c] = __float2half(u3);
    }
}

__global__ void demod_kernel() {
    int wid = (blockIdx.x * blockDim.x + threadIdx.x) >> 5;
    int lane = threadIdx.x & 31;
    int b = wid >> 9, o = wid & 511;
    float sum = 0.f;
    const float* sb = g_s + b * CC_TOT;
    const float* wq = g_wsq + o * CC_TOT;
#pragma unroll 4
    for (int j = lane; j < CC_TOT; j += 32) {
        float sv = sb[j];
        sum += wq[j] * sv * sv;
    }
#pragma unroll
    for (int off = 16; off; off >>= 1) sum += __shfl_xor_sync(0xFFFFFFFFu, sum, off);
    if (lane == 0)
        g_mult[b * OO + o] = CONV_SCALE * rsqrtf(CONV_SCALE * CONV_SCALE * sum + EPSV);
}

// ---------------- input transform: V = B^T (x*s) B -> fp16 -------------------
// block: (c-chunk 16, tile-row 32, b 8), 128 threads.
__global__ void wino_in_kernel(const float* __restrict__ x) {
    __shared__ float ds[4][32][69];
    int cc = blockIdx.x;
    int tr = blockIdx.y;
    int b  = blockIdx.z;
    int tid = threadIdx.x;
    int c_l = tid >> 2, q = tid & 3;

    for (int j = tid; j < 4 * 32 * 69; j += 128) ((float*)ds)[j] = 0.f;
    __syncthreads();

    int c = (cc << 5) + c_l;
    float sv = g_s[b * CC_TOT + c];
    const float* xp = x + ((size_t)(b * CC_TOT + c) << 12);
#pragma unroll
    for (int hi = 0; hi < 4; hi++) {
        int h = 2 * tr - 1 + hi;
        if ((unsigned)h < (unsigned)HH) {
            const float* row = xp + (h << 6) + (q << 4);
            float* dst = &ds[hi][c_l][1 + (q << 4)];
#pragma unroll
            for (int j = 0; j < 16; j += 4) {
                float4 v = *(const float4*)(row + j);
                dst[j + 0] = v.x * sv;
                dst[j + 1] = v.y * sv;
                dst[j + 2] = v.z * sv;
                dst[j + 3] = v.w * sv;
            }
        }
    }
    __syncthreads();

    int wwarp = tid >> 5, lane = tid & 31;
#pragma unroll 1
    for (int itw = 0; itw < 8; itw++) {
        int tw = wwarp * 8 + itw;
        float d[4][4];
#pragma unroll
        for (int i = 0; i < 4; i++)
#pragma unroll
            for (int j = 0; j < 4; j++)
                d[i][j] = ds[i][lane][2 * tw + j];
        float t[4][4];
#pragma unroll
        for (int j = 0; j < 4; j++) {
            t[0][j] = d[0][j] - d[2][j];
            t[1][j] = d[1][j] + d[2][j];
            t[2][j] = d[2][j] - d[1][j];
            t[3][j] = d[1][j] - d[3][j];
        }
        int tile = tr * 32 + tw;
        size_t cbase = (size_t)(cc << 5) + lane;
#pragma unroll
        for (int i = 0; i < 4; i++) {
            float v0 = t[i][0] - t[i][2];
            float v1 = t[i][1] + t[i][2];
            float v2 = t[i][2] - t[i][1];
            float v3 = t[i][1] - t[i][3];
            int p = i * 4;
            g_V[((size_t)((p + 0) * 8 + b) * 1024 + tile) * CC_TOT + cbase] = __float2half(v0);
            g_V[((size_t)((p + 1) * 8 + b) * 1024 + tile) * CC_TOT + cbase] = __float2half(v1);
            g_V[((size_t)((p + 2) * 8 + b) * 1024 + tile) * CC_TOT + cbase] = __float2half(v2);
            g_V[((size_t)((p + 3) * 8 + b) * 1024 + tile) * CC_TOT + cbase] = __float2half(v3);
        }
    }
}

// ---------------- batched GEMM: M[z] = U[z>>3] * V[z]^T ----------------------
// CTA 256 thr, tile M=128 x N=128, K=512 (16 chunks of 32). occ 2.
#define ROWB 80
#define ABUF 10240

__device__ __forceinline__ uint32_t smem_u32(const void* p) {
    uint32_t a;
    asm("{ .reg .u64 t; cvta.to.shared.u64 t, %1; cvt.u32.u64 %0, t; }"
        : "=r"(a) : "l"(p));
    return a;
}
#define CP_ASYNC16(dst, src) \
    asm volatile("cp.async.cg.shared.global [%0], [%1], 16;" \
                 :: "r"(dst), "l"(src) : "memory")
#define CP_COMMIT() asm volatile("cp.async.commit_group;" ::: "memory")
#define CP_WAIT(n)  asm volatile("cp.async.wait_group %0;" :: "n"(n) : "memory")
#define LDSM4(r0, r1, r2, r3, a) \
    asm volatile("ldmatrix.sync.aligned.m8n8.x4.shared.b16 {%0,%1,%2,%3}, [%4];" \
                 : "=r"(r0), "=r"(r1), "=r"(r2), "=r"(r3) : "r"(a))
#define MMA16816(d0, d1, d2, d3, a0, a1, a2, a3, b0, b1) \
    asm volatile("mma.sync.aligned.m16n8k16.row.col.f32.f16.f16.f32 " \
                 "{%0,%1,%2,%3}, {%4,%5,%6,%7}, {%8,%9}, {%0,%1,%2,%3};" \
                 : "+f"(d0), "+f"(d1), "+f"(d2), "+f"(d3) \
                 : "r"(a0), "r"(a1), "r"(a2), "r"(a3), "r"(b0), "r"(b1))

__global__ void __launch_bounds__(256, 2) wino_gemm_kernel() {
    __shared__ __align__(16) char sm[4 * ABUF];   // A0 A1 B0 B1
    uint32_t smb = smem_u32(sm);

    int tid  = threadIdx.x;
    int wid  = tid >> 5;
    int lane = tid & 31;
    int warp_m = wid >> 2;            // 0..1 (64 o)
    int warp_n = wid & 3;             // 0..3 (32 tiles)

    int o_base = blockIdx.x * 128;
    int n_base = blockIdx.y * 128;
    int z      = blockIdx.z;          // p*8 + b

    const __half* Abase = g_U + ((size_t)(z >> 3) * OO + o_base) * CC_TOT;
    const __half* Bbase = g_V + ((size_t)z * 1024 + n_base) * CC_TOT;

    float acc[4][4][4];
#pragma unroll
    for (int i = 0; i < 4; i++)
#pragma unroll
        for (int j = 0; j < 4; j++)
#pragma unroll
            for (int k = 0; k < 4; k++) acc[i][j][k] = 0.f;

    int f_row = tid >> 1;
    auto issue = [&](int ch, int buf) {
        int c0 = ch << 5;
        uint32_t dA = smb + (uint32_t)buf * ABUF;
        uint32_t dB = smb + 2 * ABUF + (uint32_t)buf * ABUF;
        const __half* sa = Abase + (size_t)f_row * CC_TOT + c0;
        const __half* sb = Bbase + (size_t)f_row * CC_TOT + c0;
#pragma unroll
        for (int u = 0; u < 2; u++) {
            int unit = (tid & 1) * 2 + u;
            CP_ASYNC16(dA + (uint32_t)(f_row * ROWB + unit * 16),
                       (const char*)(sa + unit * 8));
            CP_ASYNC16(dB + (uint32_t)(f_row * ROWB + unit * 16),
                       (const char*)(sb + unit * 8));
        }
        CP_COMMIT();
    };

    uint32_t a_off = (uint32_t)((warp_m * 64 + (lane & 15)) * ROWB + (lane >> 4) * 16);
    uint32_t b_off = (uint32_t)((warp_n * 32 + (lane & 15)) * ROWB + (lane >> 4) * 16);

    issue(0, 0);

#pragma unroll 1
    for (int ch = 0; ch < 16; ch++) {
        CP_WAIT(0);
        __syncthreads();
        if (ch + 1 < 16) issue(ch + 1, (ch + 1) & 1);

        uint32_t sA = smb + (uint32_t)(ch & 1) * ABUF;
        uint32_t sB = smb + 2 * ABUF + (uint32_t)(ch & 1) * ABUF;

#pragma unroll
        for (int ks = 0; ks < 2; ks++) {
            uint32_t koff = ks * 32;
            uint32_t a[4][4], bm[2][4];
#pragma unroll
            for (int mi = 0; mi < 4; mi++)
                LDSM4(a[mi][0], a[mi][1], a[mi][2], a[mi][3],
                      sA + a_off + (uint32_t)(mi * 16 * ROWB) + koff);
#pragma unroll
            for (int ni = 0; ni < 2; ni++)
                LDSM4(bm[ni][0], bm[ni][1], bm[ni][2], bm[ni][3],
                      sB + b_off + (uint32_t)(ni * 16 * ROWB) + koff);
#pragma unroll
            for (int mi = 0; mi < 4; mi++) {
#pragma unroll
                for (int ni = 0; ni < 2; ni++) {
                    MMA16816(acc[mi][ni * 2][0], acc[mi][ni * 2][1],
                             acc[mi][ni * 2][2], acc[mi][ni * 2][3],
                             a[mi][0], a[mi][1], a[mi][2], a[mi][3],
                             bm[ni][0], bm[ni][2]);
                    MMA16816(acc[mi][ni * 2 + 1][0], acc[mi][ni * 2 + 1][1],
                             acc[mi][ni * 2 + 1][2], acc[mi][ni * 2 + 1][3],
                             a[mi][0], a[mi][1], a[mi][2], a[mi][3],
                             bm[ni][1], bm[ni][3]);
                }
            }
        }
    }

    // epilogue: write fp32 M
    float* Mb = g_M + (size_t)z * OO * 1024;
#pragma unroll
    for (int mi = 0; mi < 4; mi++) {
#pragma unroll
        for (int half = 0; half < 2; half++) {
            int o = o_base + warp_m * 64 + mi * 16 + (lane >> 2) + half * 8;
            float* op = Mb + (size_t)o * 1024 + n_base + warp_n * 32 + (lane & 3) * 2;
#pragma unroll
            for (int ni = 0; ni < 4; ni++) {
                float2 v;
                v.x = acc[mi][ni][half * 2 + 0];
                v.y = acc[mi][ni][half * 2 + 1];
                *(float2*)(op + ni * 8) = v;
            }
        }
    }
}

// ---------------- output transform: out = A^T M A * demod --------------------
__global__ void wino_out_kernel(float* __restrict__ out) {
    int bo = blockIdx.x;                 // b*512 + o
    int b = bo >> 9, o = bo & 511;
    int tid = threadIdx.x;               // 256
    float m = g_mult[bo];
#pragma unroll
    for (int k = 0; k < 4; k++) {
        int tile = tid + (k << 8);
        float M[4][4];
#pragma unroll
        for (int p = 0; p < 16; p++)
            M[p >> 2][p & 3] =
                g_M[((size_t)(p * 8 + b) * OO + o) * 1024 + tile];
        float t0[4], t1[4];
#pragma unroll
        for (int j = 0; j < 4; j++) {
            t0[j] = M[0][j] + M[1][j] + M[2][j];
            t1[j] = M[1][j] - M[2][j] - M[3][j];
        }
        float y00 = t0[0] + t0[1] + t0[2];
        float y01 = t0[1] - t0[2] - t0[3];
        float y10 = t1[0] + t1[1] + t1[2];
        float y11 = t1[1] - t1[2] - t1[3];
        int trr = tile >> 5, tww = tile & 31;
        float* op = out + (((size_t)bo) << 12) + (trr * 2) * 64 + tww * 2;
        float2 v0; v0.x = y00 * m; v0.y = y01 * m;
        float2 v1; v1.x = y10 * m; v1.y = y11 * m;
        *(float2*)op = v0;
        *(float2*)(op + 64) = v1;
    }
}

// ---------------- launch -----------------------------------------------------
extern "C" void kernel_launch(void* const* d_in, const int* in_sizes, int n_in,
                              void* d_out, int out_size) {
    const float* input  = (const float*)d_in[0];   // [B,C,H,W]
    const float* style  = (const float*)d_in[1];   // [B,S]
    const float* weight = (const float*)d_in[2];   // [1,O,C,3,3]
    const float* mw     = (const float*)d_in[3];   // [C,S]
    const float* mb     = (const float*)d_in[4];   // [C]
    float* out = (float*)d_out;

    mod_kernel<<<512, 256>>>(style, mw, mb);
    wprep_kernel<<<(OO * CC_TOT + 255) / 256, 256>>>(weight);
    demod_kernel<<<512, 256>>>();
    {
        dim3 gi(16, 32, 8);
        wino_in_kernel<<<gi, 128>>>(input);
    }
    {
        dim3 gg(4, 8, 128);
        wino_gemm_kernel<<<gg, 256>>>();
    }
    wino_out_kernel<<<4096, 256>>>(out);
}

// round 8
// speedup vs baseline: 10.7745x; 1.0143x over previous
#include <cuda_runtime.h>
#include <cuda_fp16.h>
#include <cstdint>
#include <math.h>

#define BB 8
#define CC_TOT 512
#define OO 512
#define SS 512
#define HH 64
#define WW 64
#define TAPS 9

#define EPSV 1e-8f
#define CONV_SCALE 0.014731391274719739f   // 1/sqrt(4608)
#define LIN_SCALE  0.044194173824159216f   // 1/sqrt(512)

// ---------------- device scratch (static, no allocation) ---------------------
__device__ float g_s[BB * CC_TOT];            // modulation s[b][c]
__device__ float g_mult[BB * OO];             // scale*demod[b][o]
__device__ float g_wsq[OO * CC_TOT];          // sum_k w^2 [o][c]
__device__ __align__(16) __half g_U[16 * OO * CC_TOT];                 // wino W [p][o][c]
__device__ __align__(16) __half g_V[(size_t)16 * BB * 1024 * CC_TOT];  // wino X [p*8+b][tile][c]
__device__ __align__(16) float  g_M[(size_t)16 * BB * OO * 1024];      // GEMM out [p*8+b][o][tile]

// ---------------- prep kernels ----------------------------------------------
__global__ void mod_kernel(const float* __restrict__ style,
                           const float* __restrict__ mw,
                           const float* __restrict__ mb) {
    int wid = (blockIdx.x * blockDim.x + threadIdx.x) >> 5;
    int lane = threadIdx.x & 31;
    int b = wid >> 9, c = wid & 511;
    float sum = 0.f;
    const float* st = style + b * SS;
    const float* mwr = mw + c * SS;
#pragma unroll 4
    for (int j = lane; j < SS; j += 32) sum += st[j] * mwr[j];
#pragma unroll
    for (int off = 16; off; off >>= 1) sum += __shfl_xor_sync(0xFFFFFFFFu, sum, off);
    if (lane == 0) g_s[b * CC_TOT + c] = sum * LIN_SCALE + mb[c];
}

// weight: wsq + Winograd transform U = G g G^T  -> fp16 [p][o][c]
__global__ void wprep_kernel(const float* __restrict__ w) {
    int idx = blockIdx.x * blockDim.x + threadIdx.x;   // o*512 + c
    if (idx >= OO * CC_TOT) return;
    int c = idx & 511, o = idx >> 9;
    const float* wr = w + ((size_t)o * CC_TOT + c) * TAPS;
    float g[3][3];
    float sq = 0.f;
#pragma unroll
    for (int i = 0; i < 3; i++)
#pragma unroll
        for (int j = 0; j < 3; j++) {
            float v = wr[i * 3 + j];
            g[i][j] = v;
            sq += v * v;
        }
    g_wsq[o * CC_TOT + c] = sq;
    float a[4][3];
#pragma unroll
    for (int j = 0; j < 3; j++) {
        a[0][j] = g[0][j];
        a[1][j] = 0.5f * (g[0][j] + g[1][j] + g[2][j]);
        a[2][j] = 0.5f * (g[0][j] - g[1][j] + g[2][j]);
        a[3][j] = g[2][j];
    }
#pragma unroll
    for (int i = 0; i < 4; i++) {
        float u0 = a[i][0];
        float u1 = 0.5f * (a[i][0] + a[i][1] + a[i][2]);
        float u2 = 0.5f * (a[i][0] - a[i][1] + a[i][2]);
        float u3 = a[i][2];
        int p = i * 4;
        g_U[((size_t)(p + 0) * OO + o) * CC_TOT + c] = __float2half(u0);
        g_U[((size_t)(p + 1) * OO + o) * CC_TOT + c] = __float2half(u1);
        g_U[((size_t)(p + 2) * OO + o) * CC_TOT + c] = __float2half(u2);
        g_U[((size_t)(p + 3) * OO + o) * CC_TOT + c] = __float2half(u3);
    }
}

__global__ void demod_kernel() {
    int wid = (blockIdx.x * blockDim.x + threadIdx.x) >> 5;
    int lane = threadIdx.x & 31;
    int b = wid >> 9, o = wid & 511;
    float sum = 0.f;
    const float* sb = g_s + b * CC_TOT;
    const float* wq = g_wsq + o * CC_TOT;
#pragma unroll 4
    for (int j = lane; j < CC_TOT; j += 32) {
        float sv = sb[j];
        sum += wq[j] * sv * sv;
    }
#pragma unroll
    for (int off = 16; off; off >>= 1) sum += __shfl_xor_sync(0xFFFFFFFFu, sum, off);
    if (lane == 0)
        g_mult[b * OO + o] = CONV_SCALE * rsqrtf(CONV_SCALE * CONV_SCALE * sum + EPSV);
}

// ---------------- input transform: V = B^T (x*s) B -> fp16 -------------------
// block: 256 thr; (c-chunk 16, tile-row 32, b 8). Only pad cols zeroed in the
// common case; full zero for border tile-rows.
__global__ void __launch_bounds__(256) wino_in_kernel(const float* __restrict__ x) {
    __shared__ float ds[4][32][69];
    int cc = blockIdx.x;
    int tr = blockIdx.y;
    int b  = blockIdx.z;
    int tid = threadIdx.x;

    if (tr == 0 || tr == 31) {
        for (int j = tid; j < 4 * 32 * 69; j += 256) ((float*)ds)[j] = 0.f;
    } else {
        // zero pad columns {0, 65, 66}: 4 hi x 32 c x 3
        for (int j = tid; j < 4 * 32 * 3; j += 256) {
            int colsel = j % 3;
            int rest = j / 3;
            int c = rest & 31, hi = rest >> 5;
            ds[hi][c][colsel == 0 ? 0 : 64 + colsel] = 0.f;
        }
    }
    __syncthreads();

    int c_l = tid >> 3, q = tid & 7;        // c 0..31, 8-float segment
    int c = (cc << 5) + c_l;
    float sv = g_s[b * CC_TOT + c];
    const float* xp = x + ((size_t)(b * CC_TOT + c) << 12);
#pragma unroll
    for (int hi = 0; hi < 4; hi++) {
        int h = 2 * tr - 1 + hi;
        if ((unsigned)h < (unsigned)HH) {
            const float* row = xp + (h << 6) + (q << 3);
            float* dst = &ds[hi][c_l][1 + (q << 3)];
            float4 v0 = *(const float4*)row;
            float4 v1 = *(const float4*)(row + 4);
            dst[0] = v0.x * sv; dst[1] = v0.y * sv;
            dst[2] = v0.z * sv; dst[3] = v0.w * sv;
            dst[4] = v1.x * sv; dst[5] = v1.y * sv;
            dst[6] = v1.z * sv; dst[7] = v1.w * sv;
        }
    }
    __syncthreads();

    int wwarp = tid >> 5, lane = tid & 31;
#pragma unroll
    for (int itw = 0; itw < 4; itw++) {
        int tw = wwarp * 4 + itw;
        float d[4][4];
#pragma unroll
        for (int i = 0; i < 4; i++)
#pragma unroll
            for (int j = 0; j < 4; j++)
                d[i][j] = ds[i][lane][2 * tw + j];
        float t[4][4];
#pragma unroll
        for (int j = 0; j < 4; j++) {
            t[0][j] = d[0][j] - d[2][j];
            t[1][j] = d[1][j] + d[2][j];
            t[2][j] = d[2][j] - d[1][j];
            t[3][j] = d[1][j] - d[3][j];
        }
        int tile = tr * 32 + tw;
        size_t cbase = (size_t)(cc << 5) + lane;
#pragma unroll
        for (int i = 0; i < 4; i++) {
            float v0 = t[i][0] - t[i][2];
            float v1 = t[i][1] + t[i][2];
            float v2 = t[i][2] - t[i][1];
            float v3 = t[i][1] - t[i][3];
            int p = i * 4;
            g_V[((size_t)((p + 0) * 8 + b) * 1024 + tile) * CC_TOT + cbase] = __float2half(v0);
            g_V[((size_t)((p + 1) * 8 + b) * 1024 + tile) * CC_TOT + cbase] = __float2half(v1);
            g_V[((size_t)((p + 2) * 8 + b) * 1024 + tile) * CC_TOT + cbase] = __float2half(v2);
            g_V[((size_t)((p + 3) * 8 + b) * 1024 + tile) * CC_TOT + cbase] = __float2half(v3);
        }
    }
}

// ---------------- batched GEMM: M[z] = U[z>>3] * V[z]^T ----------------------
// CTA 256 thr, tile M=128 x N=128, K=512 (16 chunks of 32), 3-stage pipeline.
#define ROWB 80
#define ABUF 10240
#define NSTG 3
#define GSMEM (2 * NSTG * ABUF)   // 61440

__device__ __forceinline__ uint32_t smem_u32(const void* p) {
    uint32_t a;
    asm("{ .reg .u64 t; cvta.to.shared.u64 t, %1; cvt.u32.u64 %0, t; }"
        : "=r"(a) : "l"(p));
    return a;
}
#define CP_ASYNC16(dst, src) \
    asm volatile("cp.async.cg.shared.global [%0], [%1], 16;" \
                 :: "r"(dst), "l"(src) : "memory")
#define CP_COMMIT() asm volatile("cp.async.commit_group;" ::: "memory")
#define CP_WAIT(n)  asm volatile("cp.async.wait_group %0;" :: "n"(n) : "memory")
#define LDSM4(r0, r1, r2, r3, a) \
    asm volatile("ldmatrix.sync.aligned.m8n8.x4.shared.b16 {%0,%1,%2,%3}, [%4];" \
                 : "=r"(r0), "=r"(r1), "=r"(r2), "=r"(r3) : "r"(a))
#define MMA16816(d0, d1, d2, d3, a0, a1, a2, a3, b0, b1) \
    asm volatile("mma.sync.aligned.m16n8k16.row.col.f32.f16.f16.f32 " \
                 "{%0,%1,%2,%3}, {%4,%5,%6,%7}, {%8,%9}, {%0,%1,%2,%3};" \
                 : "+f"(d0), "+f"(d1), "+f"(d2), "+f"(d3) \
                 : "r"(a0), "r"(a1), "r"(a2), "r"(a3), "r"(b0), "r"(b1))

__global__ void __launch_bounds__(256, 2) wino_gemm_kernel() {
    extern __shared__ __align__(16) char sm[];   // A0 A1 A2 B0 B1 B2
    uint32_t smb = smem_u32(sm);

    int tid  = threadIdx.x;
    int wid  = tid >> 5;
    int lane = tid & 31;
    int warp_m = wid >> 2;            // 0..1 (64 o)
    int warp_n = wid & 3;             // 0..3 (32 tiles)

    int o_base = blockIdx.x * 128;
    int n_base = blockIdx.y * 128;
    int z      = blockIdx.z;          // p*8 + b

    const __half* Abase = g_U + ((size_t)(z >> 3) * OO + o_base) * CC_TOT;
    const __half* Bbase = g_V + ((size_t)z * 1024 + n_base) * CC_TOT;

    float acc[4][4][4];
#pragma unroll
    for (int i = 0; i < 4; i++)
#pragma unroll
        for (int j = 0; j < 4; j++)
#pragma unroll
            for (int k = 0; k < 4; k++) acc[i][j][k] = 0.f;

    int f_row = tid >> 1;
    auto issue = [&](int ch) {
        int buf = ch % NSTG;
        int c0 = ch << 5;
        uint32_t dA = smb + (uint32_t)buf * ABUF;
        uint32_t dB = smb + NSTG * ABUF + (uint32_t)buf * ABUF;
        const __half* sa = Abase + (size_t)f_row * CC_TOT + c0;
        const __half* sb = Bbase + (size_t)f_row * CC_TOT + c0;
#pragma unroll
        for (int u = 0; u < 2; u++) {
            int unit = (tid & 1) * 2 + u;
            CP_ASYNC16(dA + (uint32_t)(f_row * ROWB + unit * 16),
                       (const char*)(sa + unit * 8));
            CP_ASYNC16(dB + (uint32_t)(f_row * ROWB + unit * 16),
                       (const char*)(sb + unit * 8));
        }
        CP_COMMIT();
    };

    uint32_t a_off = (uint32_t)((warp_m * 64 + (lane & 15)) * ROWB + (lane >> 4) * 16);
    uint32_t b_off = (uint32_t)((warp_n * 32 + (lane & 15)) * ROWB + (lane >> 4) * 16);

    issue(0); issue(1); issue(2);

#pragma unroll 1
    for (int ch = 0; ch < 16; ch++) {
        CP_WAIT(NSTG - 1);
        __syncthreads();

        int buf = ch % NSTG;
        uint32_t sA = smb + (uint32_t)buf * ABUF;
        uint32_t sB = smb + NSTG * ABUF + (uint32_t)buf * ABUF;

#pragma unroll
        for (int ks = 0; ks < 2; ks++) {
            uint32_t koff = ks * 32;
            uint32_t a[4][4], bm[2][4];
#pragma unroll
            for (int mi = 0; mi < 4; mi++)
                LDSM4(a[mi][0], a[mi][1], a[mi][2], a[mi][3],
                      sA + a_off + (uint32_t)(mi * 16 * ROWB) + koff);
#pragma unroll
            for (int ni = 0; ni < 2; ni++)
                LDSM4(bm[ni][0], bm[ni][1], bm[ni][2], bm[ni][3],
                      sB + b_off + (uint32_t)(ni * 16 * ROWB) + koff);
#pragma unroll
            for (int mi = 0; mi < 4; mi++) {
#pragma unroll
                for (int ni = 0; ni < 2; ni++) {
                    MMA16816(acc[mi][ni * 2][0], acc[mi][ni * 2][1],
                             acc[mi][ni * 2][2], acc[mi][ni * 2][3],
                             a[mi][0], a[mi][1], a[mi][2], a[mi][3],
                             bm[ni][0], bm[ni][2]);
                    MMA16816(acc[mi][ni * 2 + 1][0], acc[mi][ni * 2 + 1][1],
                             acc[mi][ni * 2 + 1][2], acc[mi][ni * 2 + 1][3],
                             a[mi][0], a[mi][1], a[mi][2], a[mi][3],
                             bm[ni][1], bm[ni][3]);
                }
            }
        }
        // must finish smem reads of this buf before refilling it next iter
        __syncthreads();
        if (ch + NSTG < 16) issue(ch + NSTG); else CP_COMMIT();
    }

    // epilogue: write fp32 M
    float* Mb = g_M + (size_t)z * OO * 1024;
#pragma unroll
    for (int mi = 0; mi < 4; mi++) {
#pragma unroll
        for (int half = 0; half < 2; half++) {
            int o = o_base + warp_m * 64 + mi * 16 + (lane >> 2) + half * 8;
            float* op = Mb + (size_t)o * 1024 + n_base + warp_n * 32 + (lane & 3) * 2;
#pragma unroll
            for (int ni = 0; ni < 4; ni++) {
                float2 v;
                v.x = acc[mi][ni][half * 2 + 0];
                v.y = acc[mi][ni][half * 2 + 1];
                *(float2*)(op + ni * 8) = v;
            }
        }
    }
}

// ---------------- output transform: out = A^T M A * demod --------------------
// 1 thread = 4 consecutive tiles; all g_M reads are float4.
__global__ void __launch_bounds__(256) wino_out_kernel(float* __restrict__ out) {
    int bo = blockIdx.x;                 // b*512 + o
    int b = bo >> 9, o = bo & 511;
    int tid = threadIdx.x;               // 256
    float m = g_mult[bo];
    int t0 = tid << 2;                   // 4 tiles per thread

    float4 M4[16];
#pragma unroll
    for (int p = 0; p < 16; p++)
        M4[p] = *(const float4*)&g_M[((size_t)(p * 8 + b) * OO + o) * 1024 + t0];

    int trr = t0 >> 5, tww = t0 & 31;
    float* op = out + (((size_t)bo) << 12) + (trr * 2) * 64 + tww * 2;
    float4 r0a, r0b, r1a, r1b;
    float* r0p = (float*)&r0a;   // 8 contiguous outputs, row 0
    float* r1p = (float*)&r1a;   // row 1
#pragma unroll
    for (int j = 0; j < 4; j++) {
        float M[4][4];
#pragma unroll
        for (int p = 0; p < 16; p++)
            M[p >> 2][p & 3] = ((const float*)&M4[p])[j];
        float t0r[4], t1r[4];
#pragma unroll
        for (int k = 0; k < 4; k++) {
            t0r[k] = M[0][k] + M[1][k] + M[2][k];
            t1r[k] = M[1][k] - M[2][k] - M[3][k];
        }
        float y00 = (t0r[0] + t0r[1] + t0r[2]) * m;
        float y01 = (t0r[1] - t0r[2] - t0r[3]) * m;
        float y10 = (t1r[0] + t1r[1] + t1r[2]) * m;
        float y11 = (t1r[1] - t1r[2] - t1r[3]) * m;
        if (j < 2) {
            ((float2*)&r0a)[j] = make_float2(y00, y01);
            ((float2*)&r1a)[j] = make_float2(y10, y11);
        } else {
            ((float2*)&r0b)[j - 2] = make_float2(y00, y01);
            ((float2*)&r1b)[j - 2] = make_float2(y10, y11);
        }
    }
    (void)r0p; (void)r1p;
    *(float4*)op = r0a;
    *(float4*)(op + 4) = r0b;
    *(float4*)(op + 64) = r1a;
    *(float4*)(op + 68) = r1b;
}

// ---------------- launch -----------------------------------------------------
extern "C" void kernel_launch(void* const* d_in, const int* in_sizes, int n_in,
                              void* d_out, int out_size) {
    const float* input  = (const float*)d_in[0];   // [B,C,H,W]
    const float* style  = (const float*)d_in[1];   // [B,S]
    const float* weight = (const float*)d_in[2];   // [1,O,C,3,3]
    const float* mw     = (const float*)d_in[3];   // [C,S]
    const float* mb     = (const float*)d_in[4];   // [C]
    float* out = (float*)d_out;

    mod_kernel<<<512, 256>>>(style, mw, mb);
    wprep_kernel<<<(OO * CC_TOT + 255) / 256, 256>>>(weight);
    demod_kernel<<<512, 256>>>();
    {
        dim3 gi(16, 32, 8);
        wino_in_kernel<<<gi, 256>>>(input);
    }
    cudaFuncSetAttribute(wino_gemm_kernel,
                         cudaFuncAttributeMaxDynamicSharedMemorySize, GSMEM);
    {
        dim3 gg(4, 8, 128);
        wino_gemm_kernel<<<gg, 256, GSMEM>>>();
    }
    wino_out_kernel<<<4096, 256>>>(out);
}

// round 9
// speedup vs baseline: 11.8950x; 1.1040x over previous
#include <cuda_runtime.h>
#include <cuda_fp16.h>
#include <cstdint>
#include <math.h>

#define BB 8
#define CC_TOT 512
#define OO 512
#define SS 512
#define HH 64
#define WW 64
#define TAPS 9

#define EPSV 1e-8f
#define CONV_SCALE 0.014731391274719739f   // 1/sqrt(4608)
#define LIN_SCALE  0.044194173824159216f   // 1/sqrt(512)

// ---------------- device scratch (static, no allocation) ---------------------
__device__ float g_s[BB * CC_TOT];            // modulation s[b][c]
__device__ float g_mult[BB * OO];             // scale*demod[b][o]
__device__ float g_wsq[OO * CC_TOT];          // sum_k w^2 [o][c]
__device__ __align__(16) __half g_U[16 * OO * CC_TOT];                 // wino W [p][o][c]
__device__ __align__(16) __half g_V[(size_t)16 * BB * 1024 * CC_TOT];  // wino X [p*8+b][tile][c]
__device__ __align__(16) __half g_Mh[(size_t)16 * BB * OO * 1024];     // GEMM out fp16

// ---------------- prep kernels ----------------------------------------------
__global__ void mod_kernel(const float* __restrict__ style,
                           const float* __restrict__ mw,
                           const float* __restrict__ mb) {
    int wid = (blockIdx.x * blockDim.x + threadIdx.x) >> 5;
    int lane = threadIdx.x & 31;
    int b = wid >> 9, c = wid & 511;
    float sum = 0.f;
    const float* st = style + b * SS;
    const float* mwr = mw + c * SS;
#pragma unroll 4
    for (int j = lane; j < SS; j += 32) sum += st[j] * mwr[j];
#pragma unroll
    for (int off = 16; off; off >>= 1) sum += __shfl_xor_sync(0xFFFFFFFFu, sum, off);
    if (lane == 0) g_s[b * CC_TOT + c] = sum * LIN_SCALE + mb[c];
}

// weight: wsq + Winograd transform U = G g G^T  -> fp16 [p][o][c]
__global__ void wprep_kernel(const float* __restrict__ w) {
    int idx = blockIdx.x * blockDim.x + threadIdx.x;   // o*512 + c
    if (idx >= OO * CC_TOT) return;
    int c = idx & 511, o = idx >> 9;
    const float* wr = w + ((size_t)o * CC_TOT + c) * TAPS;
    float g[3][3];
    float sq = 0.f;
#pragma unroll
    for (int i = 0; i < 3; i++)
#pragma unroll
        for (int j = 0; j < 3; j++) {
            float v = wr[i * 3 + j];
            g[i][j] = v;
            sq += v * v;
        }
    g_wsq[o * CC_TOT + c] = sq;
    float a[4][3];
#pragma unroll
    for (int j = 0; j < 3; j++) {
        a[0][j] = g[0][j];
        a[1][j] = 0.5f * (g[0][j] + g[1][j] + g[2][j]);
        a[2][j] = 0.5f * (g[0][j] - g[1][j] + g[2][j]);
        a[3][j] = g[2][j];
    }
#pragma unroll
    for (int i = 0; i < 4; i++) {
        float u0 = a[i][0];
        float u1 = 0.5f * (a[i][0] + a[i][1] + a[i][2]);
        float u2 = 0.5f * (a[i][0] - a[i][1] + a[i][2]);
        float u3 = a[i][2];
        int p = i * 4;
        g_U[((size_t)(p + 0) * OO + o) * CC_TOT + c] = __float2half(u0);
        g_U[((size_t)(p + 1) * OO + o) * CC_TOT + c] = __float2half(u1);
        g_U[((size_t)(p + 2) * OO + o) * CC_TOT + c] = __float2half(u2);
        g_U[((size_t)(p + 3) * OO + o) * CC_TOT + c] = __float2half(u3);
    }
}

__global__ void demod_kernel() {
    int wid = (blockIdx.x * blockDim.x + threadIdx.x) >> 5;
    int lane = threadIdx.x & 31;
    int b = wid >> 9, o = wid & 511;
    float sum = 0.f;
    const float* sb = g_s + b * CC_TOT;
    const float* wq = g_wsq + o * CC_TOT;
#pragma unroll 4
    for (int j = lane; j < CC_TOT; j += 32) {
        float sv = sb[j];
        sum += wq[j] * sv * sv;
    }
#pragma unroll
    for (int off = 16; off; off >>= 1) sum += __shfl_xor_sync(0xFFFFFFFFu, sum, off);
    if (lane == 0)
        g_mult[b * OO + o] = CONV_SCALE * rsqrtf(CONV_SCALE * CONV_SCALE * sum + EPSV);
}

// ---------------- input transform: V = B^T (x*s) B -> fp16 -------------------
__global__ void __launch_bounds__(256) wino_in_kernel(const float* __restrict__ x) {
    __shared__ float ds[4][32][69];
    int cc = blockIdx.x;
    int tr = blockIdx.y;
    int b  = blockIdx.z;
    int tid = threadIdx.x;

    if (tr == 0 || tr == 31) {
        for (int j = tid; j < 4 * 32 * 69; j += 256) ((float*)ds)[j] = 0.f;
    } else {
        for (int j = tid; j < 4 * 32 * 3; j += 256) {
            int colsel = j % 3;
            int rest = j / 3;
            int c = rest & 31, hi = rest >> 5;
            ds[hi][c][colsel == 0 ? 0 : 64 + colsel] = 0.f;
        }
    }
    __syncthreads();

    int c_l = tid >> 3, q = tid & 7;        // c 0..31, 8-float segment
    int c = (cc << 5) + c_l;
    float sv = g_s[b * CC_TOT + c];
    const float* xp = x + ((size_t)(b * CC_TOT + c) << 12);
#pragma unroll
    for (int hi = 0; hi < 4; hi++) {
        int h = 2 * tr - 1 + hi;
        if ((unsigned)h < (unsigned)HH) {
            const float* row = xp + (h << 6) + (q << 3);
            float* dst = &ds[hi][c_l][1 + (q << 3)];
            float4 v0 = *(const float4*)row;
            float4 v1 = *(const float4*)(row + 4);
            dst[0] = v0.x * sv; dst[1] = v0.y * sv;
            dst[2] = v0.z * sv; dst[3] = v0.w * sv;
            dst[4] = v1.x * sv; dst[5] = v1.y * sv;
            dst[6] = v1.z * sv; dst[7] = v1.w * sv;
        }
    }
    __syncthreads();

    int wwarp = tid >> 5, lane = tid & 31;
#pragma unroll
    for (int itw = 0; itw < 4; itw++) {
        int tw = wwarp * 4 + itw;
        float d[4][4];
#pragma unroll
        for (int i = 0; i < 4; i++)
#pragma unroll
            for (int j = 0; j < 4; j++)
                d[i][j] = ds[i][lane][2 * tw + j];
        float t[4][4];
#pragma unroll
        for (int j = 0; j < 4; j++) {
            t[0][j] = d[0][j] - d[2][j];
            t[1][j] = d[1][j] + d[2][j];
            t[2][j] = d[2][j] - d[1][j];
            t[3][j] = d[1][j] - d[3][j];
        }
        int tile = tr * 32 + tw;
        size_t cbase = (size_t)(cc << 5) + lane;
#pragma unroll
        for (int i = 0; i < 4; i++) {
            float v0 = t[i][0] - t[i][2];
            float v1 = t[i][1] + t[i][2];
            float v2 = t[i][2] - t[i][1];
            float v3 = t[i][1] - t[i][3];
            int p = i * 4;
            g_V[((size_t)((p + 0) * 8 + b) * 1024 + tile) * CC_TOT + cbase] = __float2half(v0);
            g_V[((size_t)((p + 1) * 8 + b) * 1024 + tile) * CC_TOT + cbase] = __float2half(v1);
            g_V[((size_t)((p + 2) * 8 + b) * 1024 + tile) * CC_TOT + cbase] = __float2half(v2);
            g_V[((size_t)((p + 3) * 8 + b) * 1024 + tile) * CC_TOT + cbase] = __float2half(v3);
        }
    }
}

// ---------------- batched GEMM: Mh[z] = U[z>>3] * V[z]^T ---------------------
// CTA 256 thr, tile 128x128, K=512 (16 chunks of 32), 4-stage single-barrier.
#define ROWB 80
#define ABUF 10240
#define NSTG 4
#define GSMEM (2 * NSTG * ABUF)   // 81920

__device__ __forceinline__ uint32_t smem_u32(const void* p) {
    uint32_t a;
    asm("{ .reg .u64 t; cvta.to.shared.u64 t, %1; cvt.u32.u64 %0, t; }"
        : "=r"(a) : "l"(p));
    return a;
}
#define CP_ASYNC16(dst, src) \
    asm volatile("cp.async.cg.shared.global [%0], [%1], 16;" \
                 :: "r"(dst), "l"(src) : "memory")
#define CP_COMMIT() asm volatile("cp.async.commit_group;" ::: "memory")
#define CP_WAIT(n)  asm volatile("cp.async.wait_group %0;" :: "n"(n) : "memory")
#define LDSM4(r0, r1, r2, r3, a) \
    asm volatile("ldmatrix.sync.aligned.m8n8.x4.shared.b16 {%0,%1,%2,%3}, [%4];" \
                 : "=r"(r0), "=r"(r1), "=r"(r2), "=r"(r3) : "r"(a))
#define MMA16816(d0, d1, d2, d3, a0, a1, a2, a3, b0, b1) \
    asm volatile("mma.sync.aligned.m16n8k16.row.col.f32.f16.f16.f32 " \
                 "{%0,%1,%2,%3}, {%4,%5,%6,%7}, {%8,%9}, {%0,%1,%2,%3};" \
                 : "+f"(d0), "+f"(d1), "+f"(d2), "+f"(d3) \
                 : "r"(a0), "r"(a1), "r"(a2), "r"(a3), "r"(b0), "r"(b1))

__global__ void __launch_bounds__(256, 2) wino_gemm_kernel() {
    extern __shared__ __align__(16) char sm[];   // A0..A3 B0..B3
    uint32_t smb = smem_u32(sm);

    int tid  = threadIdx.x;
    int wid  = tid >> 5;
    int lane = tid & 31;
    int warp_m = wid >> 2;            // 0..1 (64 o)
    int warp_n = wid & 3;             // 0..3 (32 tiles)

    int o_base = blockIdx.x * 128;
    int n_base = blockIdx.y * 128;
    int z      = blockIdx.z;          // p*8 + b

    const __half* Abase = g_U + ((size_t)(z >> 3) * OO + o_base) * CC_TOT;
    const __half* Bbase = g_V + ((size_t)z * 1024 + n_base) * CC_TOT;

    float acc[4][4][4];
#pragma unroll
    for (int i = 0; i < 4; i++)
#pragma unroll
        for (int j = 0; j < 4; j++)
#pragma unroll
            for (int k = 0; k < 4; k++) acc[i][j][k] = 0.f;

    int f_row = tid >> 1;
    auto issue = [&](int ch) {
        int buf = ch & (NSTG - 1);
        int c0 = ch << 5;
        uint32_t dA = smb + (uint32_t)buf * ABUF;
        uint32_t dB = smb + NSTG * ABUF + (uint32_t)buf * ABUF;
        const __half* sa = Abase + (size_t)f_row * CC_TOT + c0;
        const __half* sb = Bbase + (size_t)f_row * CC_TOT + c0;
#pragma unroll
        for (int u = 0; u < 2; u++) {
            int unit = (tid & 1) * 2 + u;
            CP_ASYNC16(dA + (uint32_t)(f_row * ROWB + unit * 16),
                       (const char*)(sa + unit * 8));
            CP_ASYNC16(dB + (uint32_t)(f_row * ROWB + unit * 16),
                       (const char*)(sb + unit * 8));
        }
        CP_COMMIT();
    };

    uint32_t a_off = (uint32_t)((warp_m * 64 + (lane & 15)) * ROWB + (lane >> 4) * 16);
    uint32_t b_off = (uint32_t)((warp_n * 32 + (lane & 15)) * ROWB + (lane >> 4) * 16);

    issue(0); issue(1); issue(2);

#pragma unroll 1
    for (int ch = 0; ch < 16; ch++) {
        CP_WAIT(2);
        __syncthreads();

        int buf = ch & (NSTG - 1);
        uint32_t sA = smb + (uint32_t)buf * ABUF;
        uint32_t sB = smb + NSTG * ABUF + (uint32_t)buf * ABUF;

#pragma unroll
        for (int ks = 0; ks < 2; ks++) {
            uint32_t koff = ks * 32;
            uint32_t a[4][4], bm[2][4];
#pragma unroll
            for (int mi = 0; mi < 4; mi++)
                LDSM4(a[mi][0], a[mi][1], a[mi][2], a[mi][3],
                      sA + a_off + (uint32_t)(mi * 16 * ROWB) + koff);
#pragma unroll
            for (int ni = 0; ni < 2; ni++)
                LDSM4(bm[ni][0], bm[ni][1], bm[ni][2], bm[ni][3],
                      sB + b_off + (uint32_t)(ni * 16 * ROWB) + koff);
#pragma unroll
            for (int mi = 0; mi < 4; mi++) {
#pragma unroll
                for (int ni = 0; ni < 2; ni++) {
                    MMA16816(acc[mi][ni * 2][0], acc[mi][ni * 2][1],
                             acc[mi][ni * 2][2], acc[mi][ni * 2][3],
                             a[mi][0], a[mi][1], a[mi][2], a[mi][3],
                             bm[ni][0], bm[ni][2]);
                    MMA16816(acc[mi][ni * 2 + 1][0], acc[mi][ni * 2 + 1][1],
                             acc[mi][ni * 2 + 1][2], acc[mi][ni * 2 + 1][3],
                             a[mi][0], a[mi][1], a[mi][2], a[mi][3],
                             bm[ni][1], bm[ni][3]);
                }
            }
        }
        // issue into buf (ch+3)&3 == (ch-1)&3: consumed last iteration,
        // all warps passed this iteration's barrier after reading it -> safe.
        if (ch + 3 < 16) issue(ch + 3);
    }

    // epilogue: write fp16 M
    __half* Mb = g_Mh + (size_t)z * OO * 1024;
#pragma unroll
    for (int mi = 0; mi < 4; mi++) {
#pragma unroll
        for (int hf = 0; hf < 2; hf++) {
            int o = o_base + warp_m * 64 + mi * 16 + (lane >> 2) + hf * 8;
            __half2* op = (__half2*)(Mb + (size_t)o * 1024 + n_base +
                                     warp_n * 32 + (lane & 3) * 2);
#pragma unroll
            for (int ni = 0; ni < 4; ni++)
                op[ni * 4] = __floats2half2_rn(acc[mi][ni][hf * 2 + 0],
                                               acc[mi][ni][hf * 2 + 1]);
        }
    }
}

// ---------------- output transform: out = A^T M A * demod --------------------
// 1 thread = 4 consecutive tiles; g_Mh reads are 2x half2 (8B).
__global__ void __launch_bounds__(256) wino_out_kernel(float* __restrict__ out) {
    int bo = blockIdx.x;                 // b*512 + o
    int b = bo >> 9, o = bo & 511;
    int tid = threadIdx.x;               // 256
    float m = g_mult[bo];
    int t0 = tid << 2;                   // 4 tiles per thread

    float M4[16][4];
#pragma unroll
    for (int p = 0; p < 16; p++) {
        const __half2* src =
            (const __half2*)&g_Mh[((size_t)(p * 8 + b) * OO + o) * 1024 + t0];
        float2 f0 = __half22float2(src[0]);
        float2 f1 = __half22float2(src[1]);
        M4[p][0] = f0.x; M4[p][1] = f0.y; M4[p][2] = f1.x; M4[p][3] = f1.y;
    }

    int trr = t0 >> 5, tww = t0 & 31;
    float* op = out + (((size_t)bo) << 12) + (trr * 2) * 64 + tww * 2;
    float4 r0a, r0b, r1a, r1b;
#pragma unroll
    for (int j = 0; j < 4; j++) {
        float M[4][4];
#pragma unroll
        for (int p = 0; p < 16; p++)
            M[p >> 2][p & 3] = M4[p][j];
        float t0r[4], t1r[4];
#pragma unroll
        for (int k = 0; k < 4; k++) {
            t0r[k] = M[0][k] + M[1][k] + M[2][k];
            t1r[k] = M[1][k] - M[2][k] - M[3][k];
        }
        float y00 = (t0r[0] + t0r[1] + t0r[2]) * m;
        float y01 = (t0r[1] - t0r[2] - t0r[3]) * m;
        float y10 = (t1r[0] + t1r[1] + t1r[2]) * m;
        float y11 = (t1r[1] - t1r[2] - t1r[3]) * m;
        if (j < 2) {
            ((float2*)&r0a)[j] = make_float2(y00, y01);
            ((float2*)&r1a)[j] = make_float2(y10, y11);
        } else {
            ((float2*)&r0b)[j - 2] = make_float2(y00, y01);
            ((float2*)&r1b)[j - 2] = make_float2(y10, y11);
        }
    }
    *(float4*)op = r0a;
    *(float4*)(op + 4) = r0b;
    *(float4*)(op + 64) = r1a;
    *(float4*)(op + 68) = r1b;
}

// ---------------- launch -----------------------------------------------------
extern "C" void kernel_launch(void* const* d_in, const int* in_sizes, int n_in,
                              void* d_out, int out_size) {
    const float* input  = (const float*)d_in[0];   // [B,C,H,W]
    const float* style  = (const float*)d_in[1];   // [B,S]
    const float* weight = (const float*)d_in[2];   // [1,O,C,3,3]
    const float* mw     = (const float*)d_in[3];   // [C,S]
    const float* mb     = (const float*)d_in[4];   // [C]
    float* out = (float*)d_out;

    mod_kernel<<<512, 256>>>(style, mw, mb);
    wprep_kernel<<<(OO * CC_TOT + 255) / 256, 256>>>(weight);
    demod_kernel<<<512, 256>>>();
    {
        dim3 gi(16, 32, 8);
        wino_in_kernel<<<gi, 256>>>(input);
    }
    cudaFuncSetAttribute(wino_gemm_kernel,
                         cudaFuncAttributeMaxDynamicSharedMemorySize, GSMEM);
    {
        dim3 gg(4, 8, 128);
        wino_gemm_kernel<<<gg, 256, GSMEM>>>();
    }
    wino_out_kernel<<<4096, 256>>>(out);
}